// round 11
// baseline (speedup 1.0000x reference)
#include <cuda_runtime.h>
#include <cuda_fp16.h>
#include <cstdint>

#define SCALE_LOGIT 7.2134752044448169f   // TEMP(5) * log2(e)

// ----------------- device scratch (no allocation allowed) -----------------
__device__ __align__(16) float d_Wtp[512 * 128];
__device__ __align__(16) float d_btp[128];
__device__ __align__(16) float d_Wg[512 * 64];
__device__ __align__(16) float d_bg[64];
__device__ __align__(16) float d_W2[64 * 512];
__device__ __align__(16) float d_thetaF[4 * 9216 * 64];   // [b][n][c] fp32 scaled logits
__device__ __align__(16) float d_phiF[4 * 2304 * 64];     // [b][m][c] fp32
__device__ __align__(16) uint32_t d_thQ8hi[4 * 9216 * 16]; // [b][n][16w] s8 hi (4ch/word)
__device__ __align__(16) uint32_t d_thQ8lo[4 * 9216 * 16]; // s8 lo
__device__ __align__(16) uint32_t d_phQ8hi[4 * 2304 * 16]; // [b][m][16w]
__device__ __align__(16) uint32_t d_phQ8lo[4 * 2304 * 16];
__device__ __align__(16) uint32_t d_g2[4 * 1152 * 64];    // [b][m/2][c] half2(g[2m],g[2m+1])
__device__ __align__(16) float d_omap[4 * 64 * 9216];     // [b][c][n]
__device__ unsigned d_maxTh;
__device__ unsigned d_maxPh;

__device__ __forceinline__ float ex2f(float x) {
    float r; asm("ex2.approx.f32 %0, %1;" : "=f"(r) : "f"(x)); return r;
}
__device__ __forceinline__ void mma_fp16(float* c, const uint32_t* a, uint32_t b0, uint32_t b1) {
    asm volatile("mma.sync.aligned.m16n8k16.row.col.f32.f16.f16.f32 "
                 "{%0,%1,%2,%3},{%4,%5,%6,%7},{%8,%9},{%0,%1,%2,%3};"
                 : "+f"(c[0]), "+f"(c[1]), "+f"(c[2]), "+f"(c[3])
                 : "r"(a[0]), "r"(a[1]), "r"(a[2]), "r"(a[3]), "r"(b0), "r"(b1));
}
__device__ __forceinline__ void mma_s8(int* c, const uint32_t* a, uint32_t b0, uint32_t b1) {
    asm volatile("mma.sync.aligned.m16n8k32.row.col.s32.s8.s8.s32 "
                 "{%0,%1,%2,%3},{%4,%5,%6,%7},{%8,%9},{%0,%1,%2,%3};"
                 : "+r"(c[0]), "+r"(c[1]), "+r"(c[2]), "+r"(c[3])
                 : "r"(a[0]), "r"(a[1]), "r"(a[2]), "r"(a[3]), "r"(b0), "r"(b1));
}
__device__ __forceinline__ uint32_t pack4(int b0, int b1, int b2, int b3) {
    return (uint32_t)(b0 & 0xff) | ((uint32_t)(b1 & 0xff) << 8)
         | ((uint32_t)(b2 & 0xff) << 16) | ((uint32_t)(b3 & 0xff) << 24);
}
__device__ __forceinline__ void q15(float v, float inv, int& hi, int& lo) {
    int t = __float2int_rn(v * inv);
    hi = (t + 64) >> 7;
    lo = t - (hi << 7);
}

// ----------------- K0: init max accumulators -----------------
__global__ void init_max() {
    if (threadIdx.x == 0) { d_maxTh = 0u; d_maxPh = 0u; }
}

// ----------------- K1a: fuse theta/phi with down0 -----------------
__global__ void fuse_tp(const float* __restrict__ theta_w, const float* __restrict__ phi_w,
                        const float* __restrict__ down_w, const float* __restrict__ down_b) {
    int idx = blockIdx.x * 256 + threadIdx.x;
    int oc = idx & 127, ic = idx >> 7;
    const float* wrow = (oc < 64) ? (theta_w + oc * 128) : (phi_w + (oc - 64) * 128);
    float a0 = 0.f, a1 = 0.f, a2 = 0.f, a3 = 0.f, ab = 0.f;
    for (int c = 0; c < 128; c++) {
        float wv = wrow[c];
        float4 dv = *(const float4*)(down_w + (size_t)(c * 128 + ic) * 4);
        a0 += wv * dv.x; a1 += wv * dv.y; a2 += wv * dv.z; a3 += wv * dv.w;
        if (ic == 0) ab += wv * down_b[c];
    }
    float s = (oc < 64) ? SCALE_LOGIT : 1.f;
    d_Wtp[(ic * 4 + 0) * 128 + oc] = a0 * s;
    d_Wtp[(ic * 4 + 1) * 128 + oc] = a1 * s;
    d_Wtp[(ic * 4 + 2) * 128 + oc] = a2 * s;
    d_Wtp[(ic * 4 + 3) * 128 + oc] = a3 * s;
    if (ic == 0) d_btp[oc] = ab * s;
}

// ----------------- K1b: fuse g with down1 -----------------
__global__ void fuse_g(const float* __restrict__ g_w,
                       const float* __restrict__ down_w, const float* __restrict__ down_b) {
    int idx = blockIdx.x * 256 + threadIdx.x;
    int oc = idx & 63, ic = idx >> 6;
    const float* wrow = g_w + oc * 128;
    float a0 = 0.f, a1 = 0.f, a2 = 0.f, a3 = 0.f, ab = 0.f;
    for (int c = 0; c < 128; c++) {
        float wv = wrow[c];
        float4 dv = *(const float4*)(down_w + (size_t)(c * 128 + ic) * 4);
        a0 += wv * dv.x; a1 += wv * dv.y; a2 += wv * dv.z; a3 += wv * dv.w;
        if (ic == 0) ab += wv * down_b[c];
    }
    d_Wg[(ic * 4 + 0) * 64 + oc] = a0;
    d_Wg[(ic * 4 + 1) * 64 + oc] = a1;
    d_Wg[(ic * 4 + 2) * 64 + oc] = a2;
    d_Wg[(ic * 4 + 3) * 64 + oc] = a3;
    if (ic == 0) d_bg[oc] = ab;
}

// ----------------- K1c: fuse o_w with up_w -----------------
__global__ void fuse_w2(const float* __restrict__ o_w, const float* __restrict__ up_w) {
    int idx = blockIdx.x * 256 + threadIdx.x;
    int c2 = idx & 63, oc = idx >> 6;
    float a0 = 0.f, a1 = 0.f, a2 = 0.f, a3 = 0.f;
    for (int och = 0; och < 128; och++) {
        float wv = o_w[och * 64 + c2];
        float4 dv = *(const float4*)(up_w + (size_t)(och * 128 + oc) * 4);
        a0 += wv * dv.x; a1 += wv * dv.y; a2 += wv * dv.z; a3 += wv * dv.w;
    }
    d_W2[c2 * 512 + oc * 4 + 0] = a0;
    d_W2[c2 * 512 + oc * 4 + 1] = a1;
    d_W2[c2 * 512 + oc * 4 + 2] = a2;
    d_W2[c2 * 512 + oc * 4 + 3] = a3;
}

// ----------------- K2: fused theta+phi conv (R7 structure) + fp32 out + max -----------------
// grid (3, 24, 4), 256 threads; tile = 4 out-rows x 32 out-cols (128 px), 128 oc
__global__ __launch_bounds__(256) void conv_tp(const float* __restrict__ X) {
    __shared__ float As[32 * 128];
    __shared__ float Ws[32 * 128];
    int b = blockIdx.z, tr = blockIdx.y, tc = blockIdx.x;
    int tid = threadIdx.x;
    int ocg = tid & 15, pxg = tid >> 4;
    int rp = pxg >> 3, cq = pxg & 7;
    float acc[8][8];
    #pragma unroll
    for (int i = 0; i < 8; i++)
        #pragma unroll
        for (int u = 0; u < 8; u++) acc[i][u] = 0.f;
    const float* Xb = X + (size_t)b * 128 * 192 * 192;
    for (int icb = 0; icb < 16; icb++) {
        #pragma unroll
        for (int t = 0; t < 4; t++)
            ((float4*)Ws)[t * 256 + tid] = ((const float4*)(d_Wtp + icb * 4096))[t * 256 + tid];
        #pragma unroll
        for (int t = 0; t < 8; t++) {
            int i = t * 256 + tid;
            int jc = i & 31, p = (i >> 5) & 1, ro = (i >> 6) & 3, ic8 = i >> 8;
            float2 v = ((const float2*)(Xb + ((size_t)(icb * 8 + ic8) * 192
                         + 8 * tr + 2 * ro + p) * 192 + tc * 64))[jc];
            As[(ic8 * 4 + p * 2 + 0) * 128 + ro * 32 + jc] = v.x;
            As[(ic8 * 4 + p * 2 + 1) * 128 + ro * 32 + jc] = v.y;
        }
        __syncthreads();
        #pragma unroll 2
        for (int k = 0; k < 32; k++) {
            float4 alo = *(const float4*)(As + k * 128 + (2 * rp) * 32 + 4 * cq);
            float4 ahi = *(const float4*)(As + k * 128 + (2 * rp + 1) * 32 + 4 * cq);
            float4 w0 = *(const float4*)(Ws + k * 128 + ocg * 8);
            float4 w1 = *(const float4*)(Ws + k * 128 + ocg * 8 + 4);
            float av[8] = {alo.x, alo.y, alo.z, alo.w, ahi.x, ahi.y, ahi.z, ahi.w};
            float wv[8] = {w0.x, w0.y, w0.z, w0.w, w1.x, w1.y, w1.z, w1.w};
            #pragma unroll
            for (int px = 0; px < 8; px++)
                #pragma unroll
                for (int u = 0; u < 8; u++)
                    acc[px][u] += av[px] * wv[u];
        }
        __syncthreads();
    }
    if (ocg < 8) {   // theta: fp32 [b][n][64] + global max
        float* dst = d_thetaF + (size_t)b * 9216 * 64;
        float bb[8];
        #pragma unroll
        for (int u = 0; u < 8; u++) bb[u] = d_btp[ocg * 8 + u];
        float tmax = 0.f;
        #pragma unroll
        for (int px = 0; px < 8; px++) {
            int r2 = px >> 2, jj = px & 3;
            int n = (4 * tr + 2 * rp + r2) * 96 + tc * 32 + 4 * cq + jj;
            float v[8];
            #pragma unroll
            for (int u = 0; u < 8; u++) {
                v[u] = acc[px][u] + bb[u];
                tmax = fmaxf(tmax, fabsf(v[u]));
            }
            float* dp = dst + (size_t)n * 64 + ocg * 8;
            *(float4*)(dp)     = make_float4(v[0], v[1], v[2], v[3]);
            *(float4*)(dp + 4) = make_float4(v[4], v[5], v[6], v[7]);
        }
        atomicMax(&d_maxTh, __float_as_uint(tmax));
    } else {         // phi: maxpool 2x2 -> fp32 [b][m][64] + global max
        float pmax = 0.f;
        int m0 = (2 * tr + rp) * 48 + tc * 16 + 2 * cq;
        float* dst = d_phiF + ((size_t)b * 2304 + m0) * 64;
        #pragma unroll
        for (int u = 0; u < 8; u++) {
            int c = (ocg - 8) * 8 + u;
            float bv = d_btp[64 + c];
            float p0 = fmaxf(fmaxf(acc[0][u], acc[1][u]), fmaxf(acc[4][u], acc[5][u])) + bv;
            float p1 = fmaxf(fmaxf(acc[2][u], acc[3][u]), fmaxf(acc[6][u], acc[7][u])) + bv;
            pmax = fmaxf(pmax, fmaxf(fabsf(p0), fabsf(p1)));
            dst[c] = p0;
            dst[64 + c] = p1;
        }
        atomicMax(&d_maxPh, __float_as_uint(pmax));
    }
}

// ----------------- K3: fused g conv (R7 structure) + maxpool -> d_g2 fp16 pairs -----------------
// grid (3, 24, 4), 128 threads
__global__ __launch_bounds__(128) void conv_g(const float* __restrict__ Y) {
    __shared__ float As[32 * 128];
    __shared__ float Ws[32 * 64];
    int b = blockIdx.z, tr = blockIdx.y, tc = blockIdx.x;
    int tid = threadIdx.x;
    int ocg = tid & 7, pxg = tid >> 3;
    int rp = pxg >> 3, cq = pxg & 7;
    float acc[8][8];
    #pragma unroll
    for (int i = 0; i < 8; i++)
        #pragma unroll
        for (int u = 0; u < 8; u++) acc[i][u] = 0.f;
    const float* Yb = Y + (size_t)b * 128 * 192 * 192;
    for (int icb = 0; icb < 16; icb++) {
        #pragma unroll
        for (int t = 0; t < 4; t++)
            ((float4*)Ws)[t * 128 + tid] = ((const float4*)(d_Wg + icb * 2048))[t * 128 + tid];
        #pragma unroll
        for (int t = 0; t < 16; t++) {
            int i = t * 128 + tid;
            int jc = i & 31, p = (i >> 5) & 1, ro = (i >> 6) & 3, ic8 = i >> 8;
            float2 v = ((const float2*)(Yb + ((size_t)(icb * 8 + ic8) * 192
                         + 8 * tr + 2 * ro + p) * 192 + tc * 64))[jc];
            As[(ic8 * 4 + p * 2 + 0) * 128 + ro * 32 + jc] = v.x;
            As[(ic8 * 4 + p * 2 + 1) * 128 + ro * 32 + jc] = v.y;
        }
        __syncthreads();
        #pragma unroll 2
        for (int k = 0; k < 32; k++) {
            float4 alo = *(const float4*)(As + k * 128 + (2 * rp) * 32 + 4 * cq);
            float4 ahi = *(const float4*)(As + k * 128 + (2 * rp + 1) * 32 + 4 * cq);
            float4 w0 = *(const float4*)(Ws + k * 64 + ocg * 8);
            float4 w1 = *(const float4*)(Ws + k * 64 + ocg * 8 + 4);
            float av[8] = {alo.x, alo.y, alo.z, alo.w, ahi.x, ahi.y, ahi.z, ahi.w};
            float wv[8] = {w0.x, w0.y, w0.z, w0.w, w1.x, w1.y, w1.z, w1.w};
            #pragma unroll
            for (int px = 0; px < 8; px++)
                #pragma unroll
                for (int u = 0; u < 8; u++)
                    acc[px][u] += av[px] * wv[u];
        }
        __syncthreads();
    }
    int m0 = (2 * tr + rp) * 48 + tc * 16 + 2 * cq;   // even
    uint32_t pk[8];
    #pragma unroll
    for (int u = 0; u < 8; u++) {
        float bv = d_bg[ocg * 8 + u];
        float r0 = fmaxf(fmaxf(acc[0][u], acc[1][u]), fmaxf(acc[4][u], acc[5][u])) + bv;
        float r1 = fmaxf(fmaxf(acc[2][u], acc[3][u]), fmaxf(acc[6][u], acc[7][u])) + bv;
        __half2 h = __floats2half2_rn(r0, r1);
        pk[u] = *(uint32_t*)&h;
    }
    uint32_t* gdst = d_g2 + ((size_t)b * 1152 + (m0 >> 1)) * 64 + ocg * 8;
    *(uint4*)(gdst)     = make_uint4(pk[0], pk[1], pk[2], pk[3]);
    *(uint4*)(gdst + 4) = make_uint4(pk[4], pk[5], pk[6], pk[7]);
}

// ----------------- K3b: quantize theta to int15 (hi/lo s8) -----------------
// 147456 threads: each handles 16 channels of one row
__global__ void quant_th() {
    int i = blockIdx.x * 256 + threadIdx.x;
    int row = i >> 2, q = i & 3;
    float inv = 16000.f / __uint_as_float(d_maxTh);
    const float4* src = (const float4*)(d_thetaF + (size_t)row * 64 + q * 16);
    uint32_t hw[4], lw[4];
    #pragma unroll
    for (int j = 0; j < 4; j++) {
        float4 v = src[j];
        int h0, l0, h1, l1, h2, l2, h3, l3;
        q15(v.x, inv, h0, l0); q15(v.y, inv, h1, l1);
        q15(v.z, inv, h2, l2); q15(v.w, inv, h3, l3);
        hw[j] = pack4(h0, h1, h2, h3);
        lw[j] = pack4(l0, l1, l2, l3);
    }
    *(uint4*)(d_thQ8hi + (size_t)row * 16 + q * 4) = make_uint4(hw[0], hw[1], hw[2], hw[3]);
    *(uint4*)(d_thQ8lo + (size_t)row * 16 + q * 4) = make_uint4(lw[0], lw[1], lw[2], lw[3]);
}

// ----------------- K3c: quantize phi to int15 -----------------
__global__ void quant_ph() {
    int i = blockIdx.x * 256 + threadIdx.x;
    int row = i >> 2, q = i & 3;
    float inv = 16000.f / __uint_as_float(d_maxPh);
    const float4* src = (const float4*)(d_phiF + (size_t)row * 64 + q * 16);
    uint32_t hw[4], lw[4];
    #pragma unroll
    for (int j = 0; j < 4; j++) {
        float4 v = src[j];
        int h0, l0, h1, l1, h2, l2, h3, l3;
        q15(v.x, inv, h0, l0); q15(v.y, inv, h1, l1);
        q15(v.z, inv, h2, l2); q15(v.w, inv, h3, l3);
        hw[j] = pack4(h0, h1, h2, h3);
        lw[j] = pack4(l0, l1, l2, l3);
    }
    *(uint4*)(d_phQ8hi + (size_t)row * 16 + q * 4) = make_uint4(hw[0], hw[1], hw[2], hw[3]);
    *(uint4*)(d_phQ8lo + (size_t)row * 16 + q * 4) = make_uint4(lw[0], lw[1], lw[2], lw[3]);
}

// ----------------- K4: flash attention, int8-split QK + fp16 PV (Br=64, Bc=64, C=64) -----------------
// grid (144, 4), 128 threads (4 warps, one m16 q-row tile each). static smem 28672 B.
__global__ __launch_bounds__(128) void attn_i8() {
    __shared__ uint32_t smw[7168];
    uint32_t* Khi8 = smw;             // [64 keys][20 words] (64B data + 16B pad)
    uint32_t* Klo8 = smw + 1280;
    uint32_t* G2w  = smw + 2560;      // [32 pair-rows][72 words]
    uint32_t* P2w  = smw + 4864;      // [64 q][36 words]
    int b = blockIdx.y;
    int n0 = blockIdx.x * 64;
    int tid = threadIdx.x;
    int w = tid >> 5, lane = tid & 31;
    int g = lane >> 2, tig = lane & 3;
    int qa = n0 + w * 16 + g, qb = qa + 8;

    float sS = (__uint_as_float(d_maxTh) / 16000.f) * (__uint_as_float(d_maxPh) / 16000.f);
    float c_hh = sS * 16384.f, c_cr = sS * 128.f;

    // Q int8 fragments: 2 k32-steps, hi & lo
    uint32_t Qh[2][4], Ql[2][4];
    {
        const uint32_t* qh8 = d_thQ8hi + (size_t)b * 9216 * 16;
        const uint32_t* ql8 = d_thQ8lo + (size_t)b * 9216 * 16;
        #pragma unroll
        for (int ks = 0; ks < 2; ks++) {
            Qh[ks][0] = qh8[(size_t)qa * 16 + ks * 8 + tig];
            Qh[ks][1] = qh8[(size_t)qb * 16 + ks * 8 + tig];
            Qh[ks][2] = qh8[(size_t)qa * 16 + ks * 8 + 4 + tig];
            Qh[ks][3] = qh8[(size_t)qb * 16 + ks * 8 + 4 + tig];
            Ql[ks][0] = ql8[(size_t)qa * 16 + ks * 8 + tig];
            Ql[ks][1] = ql8[(size_t)qb * 16 + ks * 8 + tig];
            Ql[ks][2] = ql8[(size_t)qa * 16 + ks * 8 + 4 + tig];
            Ql[ks][3] = ql8[(size_t)qb * 16 + ks * 8 + 4 + tig];
        }
    }
    float mA = -1e30f, mB = -1e30f, lA = 0.f, lB = 0.f;
    float O[8][4];
    #pragma unroll
    for (int nt = 0; nt < 8; nt++)
        #pragma unroll
        for (int u = 0; u < 4; u++) O[nt][u] = 0.f;

    const uint32_t* phh8 = d_phQ8hi + (size_t)b * 2304 * 16;
    const uint32_t* phl8 = d_phQ8lo + (size_t)b * 2304 * 16;
    const uint4* gsrc = (const uint4*)(d_g2 + (size_t)b * 1152 * 64);

    for (int it = 0; it < 36; it++) {
        int m0 = it * 64;
        __syncthreads();
        #pragma unroll
        for (int t = 0; t < 8; t++) {   // K hi+lo: 1024 words each
            int i = t * 128 + tid;
            int key = i >> 4, wd = i & 15;
            Khi8[key * 20 + wd] = phh8[(size_t)(m0 + key) * 16 + wd];
            Klo8[key * 20 + wd] = phl8[(size_t)(m0 + key) * 16 + wd];
        }
        #pragma unroll
        for (int t = 0; t < 4; t++) {   // G: 32 pair-rows x 16 uint4
            int i = t * 128 + tid;
            int prow = i >> 4, c4 = (i & 15) * 4;
            *(uint4*)(G2w + prow * 72 + c4) = gsrc[((size_t)(m0 >> 1) + prow) * 16 + (i & 15)];
        }
        __syncthreads();
        // S = theta @ phi^T : int8 split (hh*2^14 + cross*2^7), m16n8k32
        int HH[8][4], CR[8][4];
        #pragma unroll
        for (int nt = 0; nt < 8; nt++) {
            HH[nt][0] = 0; HH[nt][1] = 0; HH[nt][2] = 0; HH[nt][3] = 0;
            CR[nt][0] = 0; CR[nt][1] = 0; CR[nt][2] = 0; CR[nt][3] = 0;
        }
        #pragma unroll
        for (int nt = 0; nt < 8; nt++) {
            const uint32_t* KH = Khi8 + (nt * 8 + g) * 20 + tig;
            const uint32_t* KL = Klo8 + (nt * 8 + g) * 20 + tig;
            uint32_t bh0 = KH[0], bh1 = KH[4], bh2 = KH[8], bh3 = KH[12];
            uint32_t bl0 = KL[0], bl1 = KL[4], bl2 = KL[8], bl3 = KL[12];
            mma_s8(HH[nt], Qh[0], bh0, bh1);
            mma_s8(HH[nt], Qh[1], bh2, bh3);
            mma_s8(CR[nt], Qh[0], bl0, bl1);
            mma_s8(CR[nt], Qh[1], bl2, bl3);
            mma_s8(CR[nt], Ql[0], bh0, bh1);
            mma_s8(CR[nt], Ql[1], bh2, bh3);
        }
        float S[8][4];
        #pragma unroll
        for (int nt = 0; nt < 8; nt++)
            #pragma unroll
            for (int j = 0; j < 4; j++)
                S[nt][j] = c_hh * __int2float_rn(HH[nt][j]) + c_cr * __int2float_rn(CR[nt][j]);
        // online softmax (logits in log2 domain)
        float mxA = -1e30f, mxB = -1e30f;
        #pragma unroll
        for (int nt = 0; nt < 8; nt++) {
            mxA = fmaxf(mxA, fmaxf(S[nt][0], S[nt][1]));
            mxB = fmaxf(mxB, fmaxf(S[nt][2], S[nt][3]));
        }
        mxA = fmaxf(mxA, __shfl_xor_sync(0xffffffffu, mxA, 1));
        mxA = fmaxf(mxA, __shfl_xor_sync(0xffffffffu, mxA, 2));
        mxB = fmaxf(mxB, __shfl_xor_sync(0xffffffffu, mxB, 1));
        mxB = fmaxf(mxB, __shfl_xor_sync(0xffffffffu, mxB, 2));
        float mnA = fmaxf(mA, mxA), mnB = fmaxf(mB, mxB);
        float aA = ex2f(mA - mnA), aB = ex2f(mB - mnB);
        mA = mnA; mB = mnB;
        float sumA = 0.f, sumB = 0.f;
        #pragma unroll
        for (int nt = 0; nt < 8; nt++) {
            S[nt][0] = ex2f(S[nt][0] - mA);
            S[nt][1] = ex2f(S[nt][1] - mA);
            S[nt][2] = ex2f(S[nt][2] - mB);
            S[nt][3] = ex2f(S[nt][3] - mB);
            sumA += S[nt][0] + S[nt][1];
            sumB += S[nt][2] + S[nt][3];
        }
        sumA += __shfl_xor_sync(0xffffffffu, sumA, 1);
        sumA += __shfl_xor_sync(0xffffffffu, sumA, 2);
        sumB += __shfl_xor_sync(0xffffffffu, sumB, 1);
        sumB += __shfl_xor_sync(0xffffffffu, sumB, 2);
        lA = lA * aA + sumA;
        lB = lB * aB + sumB;
        #pragma unroll
        for (int nt = 0; nt < 8; nt++) {
            O[nt][0] *= aA; O[nt][1] *= aA; O[nt][2] *= aB; O[nt][3] *= aB;
        }
        // store P as packed half2 pairs (k even, k odd) to per-warp rows
        int q0 = w * 16 + g;
        #pragma unroll
        for (int nt = 0; nt < 8; nt++) {
            __half2 hA = __floats2half2_rn(S[nt][0], S[nt][1]);
            __half2 hB = __floats2half2_rn(S[nt][2], S[nt][3]);
            P2w[q0 * 36 + 4 * nt + tig]       = *(uint32_t*)&hA;
            P2w[(q0 + 8) * 36 + 4 * nt + tig] = *(uint32_t*)&hB;
        }
        __syncwarp();
        // O += P @ G   fp16 m16n8k16
        #pragma unroll
        for (int kt = 0; kt < 4; kt++) {
            uint32_t a[4];
            const uint32_t* PR = P2w + (w * 16 + g) * 36 + kt * 8 + tig;
            a[0] = PR[0];
            a[1] = PR[8 * 36];
            a[2] = PR[4];
            a[3] = PR[8 * 36 + 4];
            const uint32_t* GR = G2w + (kt * 8 + tig) * 72 + g;
            #pragma unroll
            for (int nt = 0; nt < 8; nt++) {
                uint32_t b0 = GR[nt * 8];
                uint32_t b1 = GR[4 * 72 + nt * 8];
                mma_fp16(O[nt], a, b0, b1);
            }
        }
    }
    // normalize + transpose through smem + coalesced write to d_omap [b][c][n]
    __syncthreads();
    float* stage = (float*)smw;     // [64 ch][68 q] floats = 4352 words < 7168
    float ilA = 1.f / lA, ilB = 1.f / lB;
    int q0 = w * 16 + g;
    #pragma unroll
    for (int nt = 0; nt < 8; nt++) {
        int ch = nt * 8 + 2 * tig;
        stage[ch * 68 + q0]           = O[nt][0] * ilA;
        stage[(ch + 1) * 68 + q0]     = O[nt][1] * ilA;
        stage[ch * 68 + q0 + 8]       = O[nt][2] * ilB;
        stage[(ch + 1) * 68 + q0 + 8] = O[nt][3] * ilB;
    }
    __syncthreads();
    float* om = d_omap + (size_t)b * 64 * 9216 + n0;
    for (int i = tid; i < 1024; i += 128) {
        int ch = i >> 4, c4 = (i & 15) * 4;
        *(float4*)(om + (size_t)ch * 9216 + c4) = *(float4*)(stage + ch * 68 + c4);
    }
}

// ----------------- K5: fused (o_w o up) + bias + gamma*y -----------------
__global__ __launch_bounds__(256) void out_k(const float* __restrict__ Y,
                                             const float* __restrict__ up_b,
                                             const float* __restrict__ gammap,
                                             float* __restrict__ out) {
    extern __shared__ float sm[];
    float* Os = sm;
    float* Ws = sm + 4096;
    int tc = blockIdx.x, tr = blockIdx.y;
    int b = blockIdx.z >> 2, ocb = blockIdx.z & 3;
    int tid = threadIdx.x;
    int og = tid & 15, pg = tid >> 4;
    for (int i = tid; i < 2048; i += 256) {
        int c2 = i >> 5, r4 = i & 31;
        ((float4*)Ws)[i] = *(const float4*)(d_W2 + c2 * 512 + ocb * 128 + r4 * 4);
    }
    for (int i = tid; i < 1024; i += 256) {
        int c2 = i >> 4, s4 = i & 15;
        int r = s4 >> 3, jc = (s4 & 7) * 4;
        ((float4*)Os)[i] = *(const float4*)(d_omap + ((size_t)b * 64 + c2) * 9216
                                            + (2 * tr + r) * 96 + tc * 32 + jc);
    }
    __syncthreads();
    float acc[4][8];
    #pragma unroll
    for (int i = 0; i < 4; i++)
        #pragma unroll
        for (int u = 0; u < 8; u++) acc[i][u] = 0.f;
    #pragma unroll 4
    for (int c2 = 0; c2 < 64; c2++) {
        const float* Ar = Os + c2 * 64;
        float2 a01 = *(const float2*)(Ar + 2 * pg);
        float2 a23 = *(const float2*)(Ar + 32 + 2 * pg);
        const float* Wr = Ws + c2 * 128 + og * 8;
        float4 w0 = *(const float4*)(Wr);
        float4 w1 = *(const float4*)(Wr + 4);
        float wv[8] = {w0.x, w0.y, w0.z, w0.w, w1.x, w1.y, w1.z, w1.w};
        #pragma unroll
        for (int u = 0; u < 8; u++) {
            acc[0][u] += a01.x * wv[u];
            acc[1][u] += a01.y * wv[u];
            acc[2][u] += a23.x * wv[u];
            acc[3][u] += a23.y * wv[u];
        }
    }
    __syncthreads();
    float* stg = Ws;
    #pragma unroll
    for (int u = 0; u < 8; u++) {
        int row = og * 8 + u;
        int oc_l = row >> 2, p = (row >> 1) & 1, q = row & 1;
        #pragma unroll
        for (int px = 0; px < 4; px++) {
            int r = px >> 1;
            int jc = 2 * pg + (px & 1);
            stg[oc_l * 256 + (2 * r + p) * 64 + 2 * jc + q] = acc[px][u];
        }
    }
    __syncthreads();
    float gamma = *gammap;
    for (int i = tid; i < 2048; i += 256) {
        int col4 = i & 15, lrow = (i >> 4) & 3, oc_l = i >> 6;
        int oc = ocb * 32 + oc_l;
        size_t gaddr = (((size_t)b * 128 + oc) * 192 + (4 * tr + lrow)) * 192 + tc * 64 + col4 * 4;
        float4 s = ((float4*)stg)[oc_l * 64 + lrow * 16 + col4];
        float4 yv = *(const float4*)(Y + gaddr);
        float bb = up_b[oc];
        float4 o = make_float4(s.x + bb + gamma * yv.x, s.y + bb + gamma * yv.y,
                               s.z + bb + gamma * yv.z, s.w + bb + gamma * yv.w);
        *(float4*)(out + gaddr) = o;
    }
}

// ----------------- launch -----------------
extern "C" void kernel_launch(void* const* d_in, const int* in_sizes, int n_in,
                              void* d_out, int out_size) {
    (void)in_sizes; (void)n_in; (void)out_size;
    const float* input_x = (const float*)d_in[0];
    const float* input_y = (const float*)d_in[1];
    const float* down0_w = (const float*)d_in[2];
    const float* down0_b = (const float*)d_in[3];
    const float* down1_w = (const float*)d_in[4];
    const float* down1_b = (const float*)d_in[5];
    const float* theta_w = (const float*)d_in[6];
    const float* phi_w   = (const float*)d_in[7];
    const float* g_w     = (const float*)d_in[8];
    const float* o_w     = (const float*)d_in[9];
    const float* up_w    = (const float*)d_in[10];
    const float* up_b    = (const float*)d_in[11];
    const float* gamma   = (const float*)d_in[12];
    float* out = (float*)d_out;

    cudaFuncSetAttribute(out_k, cudaFuncAttributeMaxDynamicSharedMemorySize, 49152);

    init_max<<<1, 32>>>();
    fuse_tp<<<64, 256>>>(theta_w, phi_w, down0_w, down0_b);
    fuse_g<<<32, 256>>>(g_w, down1_w, down1_b);
    fuse_w2<<<32, 256>>>(o_w, up_w);
    conv_tp<<<dim3(3, 24, 4), 256>>>(input_x);
    conv_g<<<dim3(3, 24, 4), 128>>>(input_y);
    quant_th<<<576, 256>>>();
    quant_ph<<<144, 256>>>();
    attn_i8<<<dim3(144, 4), 128>>>();
    out_k<<<dim3(3, 48, 16), 256, 49152>>>(input_y, up_b, gamma, out);
}

// round 12
// speedup vs baseline: 1.5066x; 1.5066x over previous
#include <cuda_runtime.h>
#include <cuda_bf16.h>
#include <cuda_fp16.h>
#include <cstdint>

#define SCALE_LOGIT 7.2134752044448169f   // TEMP(5) * log2(e)

// ----------------- device scratch (no allocation allowed) -----------------
__device__ __align__(16) float d_Wtp[512 * 128];     // [k][oc]; oc<64: theta(scaled), oc>=64: phi
__device__ __align__(16) float d_btp[128];
__device__ __align__(16) float d_Wg[512 * 64];
__device__ __align__(16) float d_bg[64];
__device__ __align__(16) float d_W2[64 * 512];
__device__ __align__(16) uint32_t d_thQhi[4 * 9216 * 32];  // [b][n][c/2] bf16x2 hi (scaled logits)
__device__ __align__(16) uint32_t d_thQlo[4 * 9216 * 32];  // [b][n][c/2] bf16x2 lo
__device__ __align__(16) unsigned short d_phihi[4 * 2304 * 64]; // [b][m][c] bf16 hi
__device__ __align__(16) unsigned short d_philo[4 * 2304 * 64]; // [b][m][c] bf16 lo
__device__ __align__(16) uint32_t d_g2[4 * 1152 * 64];    // [b][m/2][c] half2(g[2m],g[2m+1])
__device__ __align__(16) float d_omap[4 * 64 * 9216];     // [b][c][n]

__device__ __forceinline__ float ex2f(float x) {
    float r; asm("ex2.approx.f32 %0, %1;" : "=f"(r) : "f"(x)); return r;
}
__device__ __forceinline__ void mma_bf16(float* c, const uint32_t* a, uint32_t b0, uint32_t b1) {
    asm volatile("mma.sync.aligned.m16n8k16.row.col.f32.bf16.bf16.f32 "
                 "{%0,%1,%2,%3},{%4,%5,%6,%7},{%8,%9},{%0,%1,%2,%3};"
                 : "+f"(c[0]), "+f"(c[1]), "+f"(c[2]), "+f"(c[3])
                 : "r"(a[0]), "r"(a[1]), "r"(a[2]), "r"(a[3]), "r"(b0), "r"(b1));
}
__device__ __forceinline__ void mma_fp16(float* c, const uint32_t* a, uint32_t b0, uint32_t b1) {
    asm volatile("mma.sync.aligned.m16n8k16.row.col.f32.f16.f16.f32 "
                 "{%0,%1,%2,%3},{%4,%5,%6,%7},{%8,%9},{%0,%1,%2,%3};"
                 : "+f"(c[0]), "+f"(c[1]), "+f"(c[2]), "+f"(c[3])
                 : "r"(a[0]), "r"(a[1]), "r"(a[2]), "r"(a[3]), "r"(b0), "r"(b1));
}
__device__ __forceinline__ void ldsm4(uint32_t* r, uint32_t addr) {
    asm volatile("ldmatrix.sync.aligned.m8n8.x4.shared.b16 {%0,%1,%2,%3}, [%4];"
                 : "=r"(r[0]), "=r"(r[1]), "=r"(r[2]), "=r"(r[3]) : "r"(addr));
}
__device__ __forceinline__ uint32_t pack_bf16x2(unsigned short lo, unsigned short hi) {
    return (uint32_t)lo | ((uint32_t)hi << 16);
}
__device__ __forceinline__ void cp16(uint32_t dst, const void* src) {
    asm volatile("cp.async.cg.shared.global [%0], [%1], 16;" :: "r"(dst), "l"(src));
}
__device__ __forceinline__ void cp_commit() { asm volatile("cp.async.commit_group;"); }

// ----------------- K1: all weight fusions in ONE launch (concurrent) -----------------
// grid 128 x 256: blocks [0,64) theta/phi, [64,96) g, [96,128) W2
__global__ void fuse_all(const float* __restrict__ theta_w, const float* __restrict__ phi_w,
                         const float* __restrict__ g_w, const float* __restrict__ o_w,
                         const float* __restrict__ down0_w, const float* __restrict__ down0_b,
                         const float* __restrict__ down1_w, const float* __restrict__ down1_b,
                         const float* __restrict__ up_w) {
    int blk = blockIdx.x;
    int tid = threadIdx.x;
    if (blk < 64) {
        int idx = blk * 256 + tid;
        int oc = idx & 127, ic = idx >> 7;
        const float* wrow = (oc < 64) ? (theta_w + oc * 128) : (phi_w + (oc - 64) * 128);
        float a0 = 0.f, a1 = 0.f, a2 = 0.f, a3 = 0.f, ab = 0.f;
        for (int c = 0; c < 128; c++) {
            float wv = wrow[c];
            float4 dv = *(const float4*)(down0_w + (size_t)(c * 128 + ic) * 4);
            a0 += wv * dv.x; a1 += wv * dv.y; a2 += wv * dv.z; a3 += wv * dv.w;
            if (ic == 0) ab += wv * down0_b[c];
        }
        float s = (oc < 64) ? SCALE_LOGIT : 1.f;
        d_Wtp[(ic * 4 + 0) * 128 + oc] = a0 * s;
        d_Wtp[(ic * 4 + 1) * 128 + oc] = a1 * s;
        d_Wtp[(ic * 4 + 2) * 128 + oc] = a2 * s;
        d_Wtp[(ic * 4 + 3) * 128 + oc] = a3 * s;
        if (ic == 0) d_btp[oc] = ab * s;
    } else if (blk < 96) {
        int idx = (blk - 64) * 256 + tid;
        int oc = idx & 63, ic = idx >> 6;
        const float* wrow = g_w + oc * 128;
        float a0 = 0.f, a1 = 0.f, a2 = 0.f, a3 = 0.f, ab = 0.f;
        for (int c = 0; c < 128; c++) {
            float wv = wrow[c];
            float4 dv = *(const float4*)(down1_w + (size_t)(c * 128 + ic) * 4);
            a0 += wv * dv.x; a1 += wv * dv.y; a2 += wv * dv.z; a3 += wv * dv.w;
            if (ic == 0) ab += wv * down1_b[c];
        }
        d_Wg[(ic * 4 + 0) * 64 + oc] = a0;
        d_Wg[(ic * 4 + 1) * 64 + oc] = a1;
        d_Wg[(ic * 4 + 2) * 64 + oc] = a2;
        d_Wg[(ic * 4 + 3) * 64 + oc] = a3;
        if (ic == 0) d_bg[oc] = ab;
    } else {
        int idx = (blk - 96) * 256 + tid;
        int c2 = idx & 63, oc = idx >> 6;
        float a0 = 0.f, a1 = 0.f, a2 = 0.f, a3 = 0.f;
        for (int och = 0; och < 128; och++) {
            float wv = o_w[och * 64 + c2];
            float4 dv = *(const float4*)(up_w + (size_t)(och * 128 + oc) * 4);
            a0 += wv * dv.x; a1 += wv * dv.y; a2 += wv * dv.z; a3 += wv * dv.w;
        }
        d_W2[c2 * 512 + oc * 4 + 0] = a0;
        d_W2[c2 * 512 + oc * 4 + 1] = a1;
        d_W2[c2 * 512 + oc * 4 + 2] = a2;
        d_W2[c2 * 512 + oc * 4 + 3] = a3;
    }
}

// ----------------- K2: fused theta+phi conv (R7 structure, measured 117us) -----------------
// grid (3, 24, 4), 256 threads; tile = 4 out-rows x 32 out-cols (128 px), 128 oc
__global__ __launch_bounds__(256) void conv_tp(const float* __restrict__ X) {
    __shared__ float As[32 * 128];
    __shared__ float Ws[32 * 128];
    int b = blockIdx.z, tr = blockIdx.y, tc = blockIdx.x;
    int tid = threadIdx.x;
    int ocg = tid & 15, pxg = tid >> 4;
    int rp = pxg >> 3, cq = pxg & 7;
    float acc[8][8];
    #pragma unroll
    for (int i = 0; i < 8; i++)
        #pragma unroll
        for (int u = 0; u < 8; u++) acc[i][u] = 0.f;
    const float* Xb = X + (size_t)b * 128 * 192 * 192;
    for (int icb = 0; icb < 16; icb++) {
        #pragma unroll
        for (int t = 0; t < 4; t++)
            ((float4*)Ws)[t * 256 + tid] = ((const float4*)(d_Wtp + icb * 4096))[t * 256 + tid];
        #pragma unroll
        for (int t = 0; t < 8; t++) {
            int i = t * 256 + tid;
            int jc = i & 31, p = (i >> 5) & 1, ro = (i >> 6) & 3, ic8 = i >> 8;
            float2 v = ((const float2*)(Xb + ((size_t)(icb * 8 + ic8) * 192
                         + 8 * tr + 2 * ro + p) * 192 + tc * 64))[jc];
            As[(ic8 * 4 + p * 2 + 0) * 128 + ro * 32 + jc] = v.x;
            As[(ic8 * 4 + p * 2 + 1) * 128 + ro * 32 + jc] = v.y;
        }
        __syncthreads();
        #pragma unroll 2
        for (int k = 0; k < 32; k++) {
            float4 alo = *(const float4*)(As + k * 128 + (2 * rp) * 32 + 4 * cq);
            float4 ahi = *(const float4*)(As + k * 128 + (2 * rp + 1) * 32 + 4 * cq);
            float4 w0 = *(const float4*)(Ws + k * 128 + ocg * 8);
            float4 w1 = *(const float4*)(Ws + k * 128 + ocg * 8 + 4);
            float av[8] = {alo.x, alo.y, alo.z, alo.w, ahi.x, ahi.y, ahi.z, ahi.w};
            float wv[8] = {w0.x, w0.y, w0.z, w0.w, w1.x, w1.y, w1.z, w1.w};
            #pragma unroll
            for (int px = 0; px < 8; px++)
                #pragma unroll
                for (int u = 0; u < 8; u++)
                    acc[px][u] += av[px] * wv[u];
        }
        __syncthreads();
    }
    if (ocg < 8) {   // theta (scaled): split-bf16 packed pairs, [b][n][32 words]
        uint32_t* qh = d_thQhi + (size_t)b * 9216 * 32;
        uint32_t* ql = d_thQlo + (size_t)b * 9216 * 32;
        float bb[8];
        #pragma unroll
        for (int u = 0; u < 8; u++) bb[u] = d_btp[ocg * 8 + u];
        #pragma unroll
        for (int px = 0; px < 8; px++) {
            int r2 = px >> 2, jj = px & 3;
            int n = (4 * tr + 2 * rp + r2) * 96 + tc * 32 + 4 * cq + jj;
            #pragma unroll
            for (int uu = 0; uu < 4; uu++) {
                float v0 = acc[px][2 * uu] + bb[2 * uu];
                float v1 = acc[px][2 * uu + 1] + bb[2 * uu + 1];
                __nv_bfloat16 h0 = __float2bfloat16_rn(v0);
                __nv_bfloat16 h1 = __float2bfloat16_rn(v1);
                __nv_bfloat16 l0 = __float2bfloat16_rn(v0 - __bfloat162float(h0));
                __nv_bfloat16 l1 = __float2bfloat16_rn(v1 - __bfloat162float(h1));
                size_t w = (size_t)n * 32 + ocg * 4 + uu;
                qh[w] = pack_bf16x2(__bfloat16_as_ushort(h0), __bfloat16_as_ushort(h1));
                ql[w] = pack_bf16x2(__bfloat16_as_ushort(l0), __bfloat16_as_ushort(l1));
            }
        }
    } else {         // phi, maxpooled 2x2: split-bf16, key-major [b][m][c]
        #pragma unroll
        for (int u = 0; u < 8; u++) {
            int c = (ocg - 8) * 8 + u;
            float bv = d_btp[64 + c];
            int m0 = (2 * tr + rp) * 48 + tc * 16 + 2 * cq;
            float p0 = fmaxf(fmaxf(acc[0][u], acc[1][u]), fmaxf(acc[4][u], acc[5][u])) + bv;
            float p1 = fmaxf(fmaxf(acc[2][u], acc[3][u]), fmaxf(acc[6][u], acc[7][u])) + bv;
            __nv_bfloat16 h0 = __float2bfloat16_rn(p0);
            __nv_bfloat16 h1 = __float2bfloat16_rn(p1);
            __nv_bfloat16 l0 = __float2bfloat16_rn(p0 - __bfloat162float(h0));
            __nv_bfloat16 l1 = __float2bfloat16_rn(p1 - __bfloat162float(h1));
            size_t a0 = ((size_t)b * 2304 + m0) * 64 + c;
            d_phihi[a0]      = __bfloat16_as_ushort(h0);
            d_philo[a0]      = __bfloat16_as_ushort(l0);
            d_phihi[a0 + 64] = __bfloat16_as_ushort(h1);
            d_philo[a0 + 64] = __bfloat16_as_ushort(l1);
        }
    }
}

// ----------------- K3: fused g conv + maxpool (R7 structure), d_g2 fp16 pairs -----------------
// grid (3, 24, 4), 128 threads
__global__ __launch_bounds__(128) void conv_g(const float* __restrict__ Y) {
    __shared__ float As[32 * 128];
    __shared__ float Ws[32 * 64];
    int b = blockIdx.z, tr = blockIdx.y, tc = blockIdx.x;
    int tid = threadIdx.x;
    int ocg = tid & 7, pxg = tid >> 3;
    int rp = pxg >> 3, cq = pxg & 7;
    float acc[8][8];
    #pragma unroll
    for (int i = 0; i < 8; i++)
        #pragma unroll
        for (int u = 0; u < 8; u++) acc[i][u] = 0.f;
    const float* Yb = Y + (size_t)b * 128 * 192 * 192;
    for (int icb = 0; icb < 16; icb++) {
        #pragma unroll
        for (int t = 0; t < 4; t++)
            ((float4*)Ws)[t * 128 + tid] = ((const float4*)(d_Wg + icb * 2048))[t * 128 + tid];
        #pragma unroll
        for (int t = 0; t < 16; t++) {
            int i = t * 128 + tid;
            int jc = i & 31, p = (i >> 5) & 1, ro = (i >> 6) & 3, ic8 = i >> 8;
            float2 v = ((const float2*)(Yb + ((size_t)(icb * 8 + ic8) * 192
                         + 8 * tr + 2 * ro + p) * 192 + tc * 64))[jc];
            As[(ic8 * 4 + p * 2 + 0) * 128 + ro * 32 + jc] = v.x;
            As[(ic8 * 4 + p * 2 + 1) * 128 + ro * 32 + jc] = v.y;
        }
        __syncthreads();
        #pragma unroll 2
        for (int k = 0; k < 32; k++) {
            float4 alo = *(const float4*)(As + k * 128 + (2 * rp) * 32 + 4 * cq);
            float4 ahi = *(const float4*)(As + k * 128 + (2 * rp + 1) * 32 + 4 * cq);
            float4 w0 = *(const float4*)(Ws + k * 64 + ocg * 8);
            float4 w1 = *(const float4*)(Ws + k * 64 + ocg * 8 + 4);
            float av[8] = {alo.x, alo.y, alo.z, alo.w, ahi.x, ahi.y, ahi.z, ahi.w};
            float wv[8] = {w0.x, w0.y, w0.z, w0.w, w1.x, w1.y, w1.z, w1.w};
            #pragma unroll
            for (int px = 0; px < 8; px++)
                #pragma unroll
                for (int u = 0; u < 8; u++)
                    acc[px][u] += av[px] * wv[u];
        }
        __syncthreads();
    }
    int m0 = (2 * tr + rp) * 48 + tc * 16 + 2 * cq;   // even key
    uint32_t pk[8];
    #pragma unroll
    for (int u = 0; u < 8; u++) {
        float bv = d_bg[ocg * 8 + u];
        float r0 = fmaxf(fmaxf(acc[0][u], acc[1][u]), fmaxf(acc[4][u], acc[5][u])) + bv;
        float r1 = fmaxf(fmaxf(acc[2][u], acc[3][u]), fmaxf(acc[6][u], acc[7][u])) + bv;
        __half2 h = __floats2half2_rn(r0, r1);
        pk[u] = *(uint32_t*)&h;
    }
    uint32_t* gdst = d_g2 + ((size_t)b * 1152 + (m0 >> 1)) * 64 + ocg * 8;
    *(uint4*)(gdst)     = make_uint4(pk[0], pk[1], pk[2], pk[3]);
    *(uint4*)(gdst + 4) = make_uint4(pk[4], pk[5], pk[6], pk[7]);
}

// ----------------- K4: flash attention, bf16-split QK + fp16 PV, cp.async double-buffered -----------------
// grid (144, 4), 128 threads (4 warps, one m16 q-row tile each)
// dyn smem (words): buf{0,1}: Khi[64x36]@+0, Klo@+2304, G2[32x72]@+4608 (stride 6912); P2w @13824
// total 16128 words = 64512 B
__global__ __launch_bounds__(128) void attn_tc() {
    extern __shared__ uint32_t smw[];
    int b = blockIdx.y;
    int n0 = blockIdx.x * 64;
    int tid = threadIdx.x;
    int w = tid >> 5, lane = tid & 31;
    int g = lane >> 2, tig = lane & 3;
    int qa = n0 + w * 16 + g, qb = qa + 8;

    uint32_t su = (uint32_t)__cvta_generic_to_shared(smw);
    uint32_t* P2w = smw + 13824;
    int lr = lane & 7, sel = lane >> 3;
    // K LDSM per-lane offset within a buffer: mats {Khi b0, Khi b1, Klo b0, Klo b1}; row stride 144B
    uint32_t koff = (uint32_t)(lr * 144 + (sel & 1) * 16 + ((sel >> 1) ? 9216 : 0));

    const uint4* phw4 = (const uint4*)d_phihi + (size_t)b * 2304 * 8;   // 8 chunks per key row
    const uint4* plw4 = (const uint4*)d_philo + (size_t)b * 2304 * 8;
    const uint4* g4   = (const uint4*)d_g2 + (size_t)b * 1152 * 16;     // 16 chunks per pair-row

    auto prefetch = [&](int m0, int buf) {
        uint32_t base = su + (uint32_t)buf * 27648u;
        #pragma unroll
        for (int t = 0; t < 4; t++) {          // K hi + lo: 512 chunks each
            int i = t * 128 + tid;
            int key = i >> 3, ch = i & 7;
            uint32_t d = (uint32_t)(key * 144 + ch * 16);
            cp16(base + d, phw4 + (size_t)(m0 + key) * 8 + ch);
            cp16(base + 9216 + d, plw4 + (size_t)(m0 + key) * 8 + ch);
        }
        #pragma unroll
        for (int t = 0; t < 4; t++) {          // G: 512 chunks
            int i = t * 128 + tid;
            int prow = i >> 4, c4 = i & 15;
            cp16(base + 18432 + (uint32_t)(prow * 288 + c4 * 16),
                 g4 + (size_t)((m0 >> 1) + prow) * 16 + c4);
        }
        cp_commit();
    };

    // Q fragments: 4 k16-steps, hi & lo packed bf16x2 (registers for whole kernel)
    uint32_t Qhi[4][4], Qlo[4][4];
    {
        const uint32_t* qh = d_thQhi + (size_t)b * 9216 * 32;
        const uint32_t* ql = d_thQlo + (size_t)b * 9216 * 32;
        #pragma unroll
        for (int ks = 0; ks < 4; ks++) {
            Qhi[ks][0] = qh[(size_t)qa * 32 + ks * 8 + tig];
            Qhi[ks][1] = qh[(size_t)qb * 32 + ks * 8 + tig];
            Qhi[ks][2] = qh[(size_t)qa * 32 + ks * 8 + tig + 4];
            Qhi[ks][3] = qh[(size_t)qb * 32 + ks * 8 + tig + 4];
            Qlo[ks][0] = ql[(size_t)qa * 32 + ks * 8 + tig];
            Qlo[ks][1] = ql[(size_t)qb * 32 + ks * 8 + tig];
            Qlo[ks][2] = ql[(size_t)qa * 32 + ks * 8 + tig + 4];
            Qlo[ks][3] = ql[(size_t)qb * 32 + ks * 8 + tig + 4];
        }
    }
    float mA = -1e30f, mB = -1e30f, lA = 0.f, lB = 0.f;
    float O[8][4];
    #pragma unroll
    for (int nt = 0; nt < 8; nt++)
        #pragma unroll
        for (int u = 0; u < 4; u++) O[nt][u] = 0.f;

    prefetch(0, 0);

    for (int it = 0; it < 36; it++) {
        int buf = it & 1;
        if (it < 35) {
            prefetch((it + 1) * 64, buf ^ 1);
            asm volatile("cp.async.wait_group 1;");
        } else {
            asm volatile("cp.async.wait_group 0;");
        }
        __syncthreads();
        uint32_t kbase = su + (uint32_t)buf * 27648u;
        uint32_t* G2w = smw + buf * 6912 + 4608;

        // S = theta @ phi^T : split-bf16 (hh + hl + lh), m16n8k16
        float S[8][4];
        #pragma unroll
        for (int nt = 0; nt < 8; nt++) {
            S[nt][0] = 0.f; S[nt][1] = 0.f; S[nt][2] = 0.f; S[nt][3] = 0.f;
        }
        #pragma unroll
        for (int ks = 0; ks < 4; ks++) {
            #pragma unroll
            for (int nt = 0; nt < 8; nt++) {
                uint32_t kf[4];
                ldsm4(kf, kbase + (uint32_t)(nt * 1152 + ks * 32) + koff);
                mma_bf16(S[nt], Qhi[ks], kf[0], kf[1]);
                mma_bf16(S[nt], Qhi[ks], kf[2], kf[3]);
                mma_bf16(S[nt], Qlo[ks], kf[0], kf[1]);
            }
        }
        // online softmax (logits in log2 domain)
        float mxA = -1e30f, mxB = -1e30f;
        #pragma unroll
        for (int nt = 0; nt < 8; nt++) {
            mxA = fmaxf(mxA, fmaxf(S[nt][0], S[nt][1]));
            mxB = fmaxf(mxB, fmaxf(S[nt][2], S[nt][3]));
        }
        mxA = fmaxf(mxA, __shfl_xor_sync(0xffffffffu, mxA, 1));
        mxA = fmaxf(mxA, __shfl_xor_sync(0xffffffffu, mxA, 2));
        mxB = fmaxf(mxB, __shfl_xor_sync(0xffffffffu, mxB, 1));
        mxB = fmaxf(mxB, __shfl_xor_sync(0xffffffffu, mxB, 2));
        float mnA = fmaxf(mA, mxA), mnB = fmaxf(mB, mxB);
        float aA = ex2f(mA - mnA), aB = ex2f(mB - mnB);
        mA = mnA; mB = mnB;
        float sumA = 0.f, sumB = 0.f;
        #pragma unroll
        for (int nt = 0; nt < 8; nt++) {
            S[nt][0] = ex2f(S[nt][0] - mA);
            S[nt][1] = ex2f(S[nt][1] - mA);
            S[nt][2] = ex2f(S[nt][2] - mB);
            S[nt][3] = ex2f(S[nt][3] - mB);
            sumA += S[nt][0] + S[nt][1];
            sumB += S[nt][2] + S[nt][3];
        }
        sumA += __shfl_xor_sync(0xffffffffu, sumA, 1);
        sumA += __shfl_xor_sync(0xffffffffu, sumA, 2);
        sumB += __shfl_xor_sync(0xffffffffu, sumB, 1);
        sumB += __shfl_xor_sync(0xffffffffu, sumB, 2);
        lA = lA * aA + sumA;
        lB = lB * aB + sumB;
        #pragma unroll
        for (int nt = 0; nt < 8; nt++) {
            O[nt][0] *= aA; O[nt][1] *= aA; O[nt][2] *= aB; O[nt][3] *= aB;
        }
        // store P as packed half2 pairs (k even, k odd) to per-warp rows
        int q0 = w * 16 + g;
        #pragma unroll
        for (int nt = 0; nt < 8; nt++) {
            __half2 hA = __floats2half2_rn(S[nt][0], S[nt][1]);
            __half2 hB = __floats2half2_rn(S[nt][2], S[nt][3]);
            P2w[q0 * 36 + 4 * nt + tig]       = *(uint32_t*)&hA;
            P2w[(q0 + 8) * 36 + 4 * nt + tig] = *(uint32_t*)&hB;
        }
        __syncwarp();
        // O += P @ G   fp16 m16n8k16 (scalar frags, conflict-free)
        #pragma unroll
        for (int kt = 0; kt < 4; kt++) {
            uint32_t a[4];
            const uint32_t* PR = P2w + (w * 16 + g) * 36 + kt * 8 + tig;
            a[0] = PR[0];
            a[1] = PR[8 * 36];
            a[2] = PR[4];
            a[3] = PR[8 * 36 + 4];
            const uint32_t* GR = G2w + (kt * 8 + tig) * 72 + g;
            #pragma unroll
            for (int nt = 0; nt < 8; nt++) {
                uint32_t b0 = GR[nt * 8];
                uint32_t b1 = GR[4 * 72 + nt * 8];
                mma_fp16(O[nt], a, b0, b1);
            }
        }
        __syncthreads();   // all reads of buf done before it+1 issues prefetch into it
    }
    // normalize + transpose through smem + coalesced write to d_omap [b][c][n]
    float* stage = (float*)smw;     // [64 ch][68 q] = 4352 words
    float ilA = 1.f / lA, ilB = 1.f / lB;
    int q0 = w * 16 + g;
    #pragma unroll
    for (int nt = 0; nt < 8; nt++) {
        int ch = nt * 8 + 2 * tig;
        stage[ch * 68 + q0]           = O[nt][0] * ilA;
        stage[(ch + 1) * 68 + q0]     = O[nt][1] * ilA;
        stage[ch * 68 + q0 + 8]       = O[nt][2] * ilB;
        stage[(ch + 1) * 68 + q0 + 8] = O[nt][3] * ilB;
    }
    __syncthreads();
    float* om = d_omap + (size_t)b * 64 * 9216 + n0;
    for (int i = tid; i < 1024; i += 128) {
        int ch = i >> 4, c4 = (i & 15) * 4;
        *(float4*)(om + (size_t)ch * 9216 + c4) = *(float4*)(stage + ch * 68 + c4);
    }
}

// ----------------- K5: fused (o_w o up) + bias + gamma*y, coalesced out -----------------
__global__ __launch_bounds__(256) void out_k(const float* __restrict__ Y,
                                             const float* __restrict__ up_b,
                                             const float* __restrict__ gammap,
                                             float* __restrict__ out) {
    extern __shared__ float sm[];
    float* Os = sm;
    float* Ws = sm + 4096;
    int tc = blockIdx.x, tr = blockIdx.y;
    int b = blockIdx.z >> 2, ocb = blockIdx.z & 3;
    int tid = threadIdx.x;
    int og = tid & 15, pg = tid >> 4;
    for (int i = tid; i < 2048; i += 256) {
        int c2 = i >> 5, r4 = i & 31;
        ((float4*)Ws)[i] = *(const float4*)(d_W2 + c2 * 512 + ocb * 128 + r4 * 4);
    }
    for (int i = tid; i < 1024; i += 256) {
        int c2 = i >> 4, s4 = i & 15;
        int r = s4 >> 3, jc = (s4 & 7) * 4;
        ((float4*)Os)[i] = *(const float4*)(d_omap + ((size_t)b * 64 + c2) * 9216
                                            + (2 * tr + r) * 96 + tc * 32 + jc);
    }
    __syncthreads();
    float acc[4][8];
    #pragma unroll
    for (int i = 0; i < 4; i++)
        #pragma unroll
        for (int u = 0; u < 8; u++) acc[i][u] = 0.f;
    #pragma unroll 4
    for (int c2 = 0; c2 < 64; c2++) {
        const float* Ar = Os + c2 * 64;
        float2 a01 = *(const float2*)(Ar + 2 * pg);
        float2 a23 = *(const float2*)(Ar + 32 + 2 * pg);
        const float* Wr = Ws + c2 * 128 + og * 8;
        float4 w0 = *(const float4*)(Wr);
        float4 w1 = *(const float4*)(Wr + 4);
        float wv[8] = {w0.x, w0.y, w0.z, w0.w, w1.x, w1.y, w1.z, w1.w};
        #pragma unroll
        for (int u = 0; u < 8; u++) {
            acc[0][u] += a01.x * wv[u];
            acc[1][u] += a01.y * wv[u];
            acc[2][u] += a23.x * wv[u];
            acc[3][u] += a23.y * wv[u];
        }
    }
    __syncthreads();
    float* stg = Ws;
    #pragma unroll
    for (int u = 0; u < 8; u++) {
        int row = og * 8 + u;
        int oc_l = row >> 2, p = (row >> 1) & 1, q = row & 1;
        #pragma unroll
        for (int px = 0; px < 4; px++) {
            int r = px >> 1;
            int jc = 2 * pg + (px & 1);
            stg[oc_l * 256 + (2 * r + p) * 64 + 2 * jc + q] = acc[px][u];
        }
    }
    __syncthreads();
    float gamma = *gammap;
    for (int i = tid; i < 2048; i += 256) {
        int col4 = i & 15, lrow = (i >> 4) & 3, oc_l = i >> 6;
        int oc = ocb * 32 + oc_l;
        size_t gaddr = (((size_t)b * 128 + oc) * 192 + (4 * tr + lrow)) * 192 + tc * 64 + col4 * 4;
        float4 s = ((float4*)stg)[oc_l * 64 + lrow * 16 + col4];
        float4 yv = *(const float4*)(Y + gaddr);
        float bb = up_b[oc];
        float4 o = make_float4(s.x + bb + gamma * yv.x, s.y + bb + gamma * yv.y,
                               s.z + bb + gamma * yv.z, s.w + bb + gamma * yv.w);
        *(float4*)(out + gaddr) = o;
    }
}

// ----------------- launch -----------------
extern "C" void kernel_launch(void* const* d_in, const int* in_sizes, int n_in,
                              void* d_out, int out_size) {
    (void)in_sizes; (void)n_in; (void)out_size;
    const float* input_x = (const float*)d_in[0];
    const float* input_y = (const float*)d_in[1];
    const float* down0_w = (const float*)d_in[2];
    const float* down0_b = (const float*)d_in[3];
    const float* down1_w = (const float*)d_in[4];
    const float* down1_b = (const float*)d_in[5];
    const float* theta_w = (const float*)d_in[6];
    const float* phi_w   = (const float*)d_in[7];
    const float* g_w     = (const float*)d_in[8];
    const float* o_w     = (const float*)d_in[9];
    const float* up_w    = (const float*)d_in[10];
    const float* up_b    = (const float*)d_in[11];
    const float* gamma   = (const float*)d_in[12];
    float* out = (float*)d_out;

    cudaFuncSetAttribute(attn_tc, cudaFuncAttributeMaxDynamicSharedMemorySize, 64512);
    cudaFuncSetAttribute(out_k, cudaFuncAttributeMaxDynamicSharedMemorySize, 49152);

    fuse_all<<<128, 256>>>(theta_w, phi_w, g_w, o_w,
                           down0_w, down0_b, down1_w, down1_b, up_w);
    conv_tp<<<dim3(3, 24, 4), 256>>>(input_x);
    conv_g<<<dim3(3, 24, 4), 128>>>(input_y);
    attn_tc<<<dim3(144, 4), 128, 64512>>>();
    out_k<<<dim3(3, 48, 16), 256, 49152>>>(input_y, up_b, gamma, out);
}

// round 13
// speedup vs baseline: 1.6249x; 1.0785x over previous
#include <cuda_runtime.h>
#include <cuda_bf16.h>
#include <cuda_fp16.h>
#include <cstdint>

#define SCALE_LOGIT 7.2134752044448169f   // TEMP(5) * log2(e)

// ----------------- device scratch (no allocation allowed) -----------------
__device__ __align__(16) uint32_t d_WtpH[256 * 128]; // [kpair][oc] bf16x2 hi (theta scaled | phi)
__device__ __align__(16) uint32_t d_WtpL[256 * 128]; // [kpair][oc] bf16x2 lo
__device__ __align__(16) float d_btp[128];
__device__ __align__(16) float d_Wg[512 * 64];
__device__ __align__(16) float d_bg[64];
__device__ __align__(16) float d_W2[64 * 512];
__device__ __align__(16) uint32_t d_thQhi[4 * 9216 * 32];  // [b][n][c/2] bf16x2 hi (scaled logits)
__device__ __align__(16) uint32_t d_thQlo[4 * 9216 * 32];  // [b][n][c/2] bf16x2 lo
__device__ __align__(16) unsigned short d_phihi[4 * 2304 * 64]; // [b][m][c] bf16 hi
__device__ __align__(16) unsigned short d_philo[4 * 2304 * 64]; // [b][m][c] bf16 lo
__device__ __align__(16) uint32_t d_g2[4 * 1152 * 64];    // [b][m/2][c] half2(g[2m],g[2m+1])
__device__ __align__(16) float d_omap[4 * 64 * 9216];     // [b][c][n]

__device__ __forceinline__ float ex2f(float x) {
    float r; asm("ex2.approx.f32 %0, %1;" : "=f"(r) : "f"(x)); return r;
}
__device__ __forceinline__ void mma_bf16(float* c, const uint32_t* a, uint32_t b0, uint32_t b1) {
    asm volatile("mma.sync.aligned.m16n8k16.row.col.f32.bf16.bf16.f32 "
                 "{%0,%1,%2,%3},{%4,%5,%6,%7},{%8,%9},{%0,%1,%2,%3};"
                 : "+f"(c[0]), "+f"(c[1]), "+f"(c[2]), "+f"(c[3])
                 : "r"(a[0]), "r"(a[1]), "r"(a[2]), "r"(a[3]), "r"(b0), "r"(b1));
}
__device__ __forceinline__ void mma_fp16(float* c, const uint32_t* a, uint32_t b0, uint32_t b1) {
    asm volatile("mma.sync.aligned.m16n8k16.row.col.f32.f16.f16.f32 "
                 "{%0,%1,%2,%3},{%4,%5,%6,%7},{%8,%9},{%0,%1,%2,%3};"
                 : "+f"(c[0]), "+f"(c[1]), "+f"(c[2]), "+f"(c[3])
                 : "r"(a[0]), "r"(a[1]), "r"(a[2]), "r"(a[3]), "r"(b0), "r"(b1));
}
__device__ __forceinline__ void ldsm4(uint32_t* r, uint32_t addr) {
    asm volatile("ldmatrix.sync.aligned.m8n8.x4.shared.b16 {%0,%1,%2,%3}, [%4];"
                 : "=r"(r[0]), "=r"(r[1]), "=r"(r[2]), "=r"(r[3]) : "r"(addr));
}
__device__ __forceinline__ uint32_t pack_bf16x2(unsigned short lo, unsigned short hi) {
    return (uint32_t)lo | ((uint32_t)hi << 16);
}
__device__ __forceinline__ uint32_t splitH(float a, float b, uint32_t& lo) {
    __nv_bfloat16 ha = __float2bfloat16_rn(a);
    __nv_bfloat16 hb = __float2bfloat16_rn(b);
    __nv_bfloat16 la = __float2bfloat16_rn(a - __bfloat162float(ha));
    __nv_bfloat16 lb = __float2bfloat16_rn(b - __bfloat162float(hb));
    lo = pack_bf16x2(__bfloat16_as_ushort(la), __bfloat16_as_ushort(lb));
    return pack_bf16x2(__bfloat16_as_ushort(ha), __bfloat16_as_ushort(hb));
}
__device__ __forceinline__ void cp16(uint32_t dst, const void* src) {
    asm volatile("cp.async.cg.shared.global [%0], [%1], 16;" :: "r"(dst), "l"(src));
}
__device__ __forceinline__ void cp_commit() { asm volatile("cp.async.commit_group;"); }

// ----------------- K1: all weight fusions in ONE launch -----------------
// grid 128 x 256: blocks [0,64) theta/phi (split-bf16 pair layout), [64,96) g, [96,128) W2
__global__ void fuse_all(const float* __restrict__ theta_w, const float* __restrict__ phi_w,
                         const float* __restrict__ g_w, const float* __restrict__ o_w,
                         const float* __restrict__ down0_w, const float* __restrict__ down0_b,
                         const float* __restrict__ down1_w, const float* __restrict__ down1_b,
                         const float* __restrict__ up_w) {
    int blk = blockIdx.x;
    int tid = threadIdx.x;
    if (blk < 64) {
        int idx = blk * 256 + tid;
        int oc = idx & 127, ic = idx >> 7;
        const float* wrow = (oc < 64) ? (theta_w + oc * 128) : (phi_w + (oc - 64) * 128);
        float a0 = 0.f, a1 = 0.f, a2 = 0.f, a3 = 0.f, ab = 0.f;
        for (int c = 0; c < 128; c++) {
            float wv = wrow[c];
            float4 dv = *(const float4*)(down0_w + (size_t)(c * 128 + ic) * 4);
            a0 += wv * dv.x; a1 += wv * dv.y; a2 += wv * dv.z; a3 += wv * dv.w;
            if (ic == 0) ab += wv * down0_b[c];
        }
        float s = (oc < 64) ? SCALE_LOGIT : 1.f;
        uint32_t l0, l1;
        uint32_t h0 = splitH(a0 * s, a1 * s, l0);   // kpair ic*2   (p=0: q0,q1)
        uint32_t h1 = splitH(a2 * s, a3 * s, l1);   // kpair ic*2+1 (p=1)
        d_WtpH[(ic * 2 + 0) * 128 + oc] = h0;
        d_WtpL[(ic * 2 + 0) * 128 + oc] = l0;
        d_WtpH[(ic * 2 + 1) * 128 + oc] = h1;
        d_WtpL[(ic * 2 + 1) * 128 + oc] = l1;
        if (ic == 0) d_btp[oc] = ab * s;
    } else if (blk < 96) {
        int idx = (blk - 64) * 256 + tid;
        int oc = idx & 63, ic = idx >> 6;
        const float* wrow = g_w + oc * 128;
        float a0 = 0.f, a1 = 0.f, a2 = 0.f, a3 = 0.f, ab = 0.f;
        for (int c = 0; c < 128; c++) {
            float wv = wrow[c];
            float4 dv = *(const float4*)(down1_w + (size_t)(c * 128 + ic) * 4);
            a0 += wv * dv.x; a1 += wv * dv.y; a2 += wv * dv.z; a3 += wv * dv.w;
            if (ic == 0) ab += wv * down1_b[c];
        }
        d_Wg[(ic * 4 + 0) * 64 + oc] = a0;
        d_Wg[(ic * 4 + 1) * 64 + oc] = a1;
        d_Wg[(ic * 4 + 2) * 64 + oc] = a2;
        d_Wg[(ic * 4 + 3) * 64 + oc] = a3;
        if (ic == 0) d_bg[oc] = ab;
    } else {
        int idx = (blk - 96) * 256 + tid;
        int c2 = idx & 63, oc = idx >> 6;
        float a0 = 0.f, a1 = 0.f, a2 = 0.f, a3 = 0.f;
        for (int och = 0; och < 128; och++) {
            float wv = o_w[och * 64 + c2];
            float4 dv = *(const float4*)(up_w + (size_t)(och * 128 + oc) * 4);
            a0 += wv * dv.x; a1 += wv * dv.y; a2 += wv * dv.z; a3 += wv * dv.w;
        }
        d_W2[c2 * 512 + oc * 4 + 0] = a0;
        d_W2[c2 * 512 + oc * 4 + 1] = a1;
        d_W2[c2 * 512 + oc * 4 + 2] = a2;
        d_W2[c2 * 512 + oc * 4 + 3] = a3;
    }
}

// ----------------- K2: theta+phi conv via split-bf16 tensor cores -----------------
// grid (3, 24, 4), 256 threads (8 warps). Out tile: 128 oc x 128 px (4 rows x 32 cols), K=512.
// dyn smem 67584 B: per buffer (stride 33792): WH@0, WL@8448, XH@16896, XL@25344 (rows stride 132 words).
// Epilogue reuses smem as Cs[128 oc][132] fp32.
__global__ __launch_bounds__(256) void conv_tp(const float* __restrict__ X) {
    extern __shared__ uint32_t smw[];
    int b = blockIdx.z, tr = blockIdx.y, tc = blockIdx.x;
    int tid = threadIdx.x;
    int w = tid >> 5, lane = tid & 31;
    int g = lane >> 2, tig = lane & 3;
    int w16 = w * 16;
    const float* Xb = X + (size_t)b * 128 * 192 * 192;
    uint32_t su = (uint32_t)__cvta_generic_to_shared(smw);

    float acc[16][4];
    #pragma unroll
    for (int nt = 0; nt < 16; nt++)
        #pragma unroll
        for (int u = 0; u < 4; u++) acc[nt][u] = 0.f;

    auto issueW = [&](int icb, int buf) {
        uint32_t base = su + (uint32_t)buf * 33792u;
        #pragma unroll
        for (int t = 0; t < 2; t++) {
            int i = t * 256 + tid;            // 512 chunks of 16B per type
            int row = i >> 5, seg = i & 31;
            cp16(base + (uint32_t)(row * 528 + seg * 16),
                 d_WtpH + (size_t)(icb * 16 + row) * 128 + seg * 4);
            cp16(base + 8448u + (uint32_t)(row * 528 + seg * 16),
                 d_WtpL + (size_t)(icb * 16 + row) * 128 + seg * 4);
        }
        cp_commit();
    };
    // X register prefetch: 8 float2 per thread per chunk
    float2 xr[8];
    auto loadX = [&](int icb) {
        #pragma unroll
        for (int t = 0; t < 8; t++) {
            int i = t * 256 + tid;
            int jc = i & 31, ro = (i >> 5) & 3, p = (i >> 7) & 1, lic = i >> 8;
            xr[t] = ((const float2*)(Xb + ((size_t)(icb * 8 + lic) * 192
                       + 8 * tr + 2 * ro + p) * 192 + tc * 64))[jc];
        }
    };
    auto stsX = [&](int buf) {
        uint32_t* XH = smw + buf * 8448 + 4224;
        uint32_t* XL = XH + 2112;
        #pragma unroll
        for (int t = 0; t < 8; t++) {
            int i = t * 256 + tid;
            int jc = i & 31, ro = (i >> 5) & 3, p = (i >> 7) & 1, lic = i >> 8;
            int kk = lic * 2 + p, px = ro * 32 + jc;
            uint32_t lo;
            uint32_t hi = splitH(xr[t].x, xr[t].y, lo);
            XH[kk * 132 + px] = hi;
            XL[kk * 132 + px] = lo;
        }
    };

    issueW(0, 0);
    loadX(0);
    asm volatile("cp.async.wait_group 0;");
    stsX(0);
    __syncthreads();

    for (int icb = 0; icb < 16; icb++) {
        int buf = icb & 1;
        if (icb < 15) { issueW(icb + 1, buf ^ 1); loadX(icb + 1); }
        const uint32_t* WH = smw + buf * 8448;
        const uint32_t* WL = WH + 2112;
        const uint32_t* XH = WH + 4224;
        const uint32_t* XL = WH + 6336;
        #pragma unroll
        for (int ks = 0; ks < 2; ks++) {
            uint32_t ah[4], al[4];
            const uint32_t* W0 = WH + (ks * 8 + tig) * 132;
            const uint32_t* W1 = WH + (ks * 8 + 4 + tig) * 132;
            ah[0] = W0[w16 + g]; ah[1] = W0[w16 + g + 8];
            ah[2] = W1[w16 + g]; ah[3] = W1[w16 + g + 8];
            const uint32_t* V0 = WL + (ks * 8 + tig) * 132;
            const uint32_t* V1 = WL + (ks * 8 + 4 + tig) * 132;
            al[0] = V0[w16 + g]; al[1] = V0[w16 + g + 8];
            al[2] = V1[w16 + g]; al[3] = V1[w16 + g + 8];
            const uint32_t* B0 = XH + (ks * 8 + tig) * 132 + g;
            const uint32_t* B1 = XH + (ks * 8 + 4 + tig) * 132 + g;
            const uint32_t* C0 = XL + (ks * 8 + tig) * 132 + g;
            const uint32_t* C1 = XL + (ks * 8 + 4 + tig) * 132 + g;
            #pragma unroll
            for (int nt = 0; nt < 16; nt++) {
                uint32_t bh0 = B0[nt * 8], bh1 = B1[nt * 8];
                uint32_t bl0 = C0[nt * 8], bl1 = C1[nt * 8];
                mma_bf16(acc[nt], ah, bh0, bh1);
                mma_bf16(acc[nt], ah, bl0, bl1);
                mma_bf16(acc[nt], al, bh0, bh1);
            }
        }
        if (icb < 15) {
            __syncthreads();
            stsX(buf ^ 1);
            asm volatile("cp.async.wait_group 0;");
            __syncthreads();
        }
    }
    __syncthreads();
    // stage C -> smem [128 oc][132]
    float* Cs = (float*)smw;
    #pragma unroll
    for (int nt = 0; nt < 16; nt++) {
        int col = nt * 8 + 2 * tig;
        Cs[(w16 + g) * 132 + col]       = acc[nt][0];
        Cs[(w16 + g) * 132 + col + 1]   = acc[nt][1];
        Cs[(w16 + g + 8) * 132 + col]     = acc[nt][2];
        Cs[(w16 + g + 8) * 132 + col + 1] = acc[nt][3];
    }
    __syncthreads();
    // theta epilogue: oc 0..63, 128 px x 32 words
    {
        uint32_t* qh = d_thQhi + (size_t)b * 9216 * 32;
        uint32_t* ql = d_thQlo + (size_t)b * 9216 * 32;
        #pragma unroll
        for (int j = 0; j < 16; j++) {
            int idx = j * 256 + tid;
            int px = idx & 127, wd = idx >> 7;
            int c0 = 2 * wd;
            float v0 = Cs[c0 * 132 + px] + d_btp[c0];
            float v1 = Cs[(c0 + 1) * 132 + px] + d_btp[c0 + 1];
            int ro = px >> 5, jc = px & 31;
            int n = (4 * tr + ro) * 96 + tc * 32 + jc;
            uint32_t lo;
            uint32_t hi = splitH(v0, v1, lo);
            qh[(size_t)n * 32 + wd] = hi;
            ql[(size_t)n * 32 + wd] = lo;
        }
    }
    // phi epilogue: oc 64..127, maxpool 2x2 -> 32 keys x 64 ch
    {
        #pragma unroll
        for (int j = 0; j < 8; j++) {
            int idx = j * 256 + tid;
            int c = idx & 63, pm = idx >> 6;
            int rp = pm >> 4, cqp = pm & 15;
            const float* Cr = Cs + (64 + c) * 132 + (2 * rp) * 32 + 2 * cqp;
            float v = fmaxf(fmaxf(Cr[0], Cr[1]), fmaxf(Cr[32], Cr[33])) + d_btp[64 + c];
            int m = (2 * tr + rp) * 48 + tc * 16 + cqp;
            __nv_bfloat16 h = __float2bfloat16_rn(v);
            __nv_bfloat16 l = __float2bfloat16_rn(v - __bfloat162float(h));
            size_t a0 = ((size_t)b * 2304 + m) * 64 + c;
            d_phihi[a0] = __bfloat16_as_ushort(h);
            d_philo[a0] = __bfloat16_as_ushort(l);
        }
    }
}

// ----------------- K3: fused g conv + maxpool (unchanged from R12) -----------------
__global__ __launch_bounds__(128) void conv_g(const float* __restrict__ Y) {
    __shared__ float As[32 * 128];
    __shared__ float Ws[32 * 64];
    int b = blockIdx.z, tr = blockIdx.y, tc = blockIdx.x;
    int tid = threadIdx.x;
    int ocg = tid & 7, pxg = tid >> 3;
    int rp = pxg >> 3, cq = pxg & 7;
    float acc[8][8];
    #pragma unroll
    for (int i = 0; i < 8; i++)
        #pragma unroll
        for (int u = 0; u < 8; u++) acc[i][u] = 0.f;
    const float* Yb = Y + (size_t)b * 128 * 192 * 192;
    for (int icb = 0; icb < 16; icb++) {
        #pragma unroll
        for (int t = 0; t < 4; t++)
            ((float4*)Ws)[t * 128 + tid] = ((const float4*)(d_Wg + icb * 2048))[t * 128 + tid];
        #pragma unroll
        for (int t = 0; t < 16; t++) {
            int i = t * 128 + tid;
            int jc = i & 31, p = (i >> 5) & 1, ro = (i >> 6) & 3, ic8 = i >> 8;
            float2 v = ((const float2*)(Yb + ((size_t)(icb * 8 + ic8) * 192
                         + 8 * tr + 2 * ro + p) * 192 + tc * 64))[jc];
            As[(ic8 * 4 + p * 2 + 0) * 128 + ro * 32 + jc] = v.x;
            As[(ic8 * 4 + p * 2 + 1) * 128 + ro * 32 + jc] = v.y;
        }
        __syncthreads();
        #pragma unroll 2
        for (int k = 0; k < 32; k++) {
            float4 alo = *(const float4*)(As + k * 128 + (2 * rp) * 32 + 4 * cq);
            float4 ahi = *(const float4*)(As + k * 128 + (2 * rp + 1) * 32 + 4 * cq);
            float4 w0 = *(const float4*)(Ws + k * 64 + ocg * 8);
            float4 w1 = *(const float4*)(Ws + k * 64 + ocg * 8 + 4);
            float av[8] = {alo.x, alo.y, alo.z, alo.w, ahi.x, ahi.y, ahi.z, ahi.w};
            float wv[8] = {w0.x, w0.y, w0.z, w0.w, w1.x, w1.y, w1.z, w1.w};
            #pragma unroll
            for (int px = 0; px < 8; px++)
                #pragma unroll
                for (int u = 0; u < 8; u++)
                    acc[px][u] += av[px] * wv[u];
        }
        __syncthreads();
    }
    int m0 = (2 * tr + rp) * 48 + tc * 16 + 2 * cq;
    uint32_t pk[8];
    #pragma unroll
    for (int u = 0; u < 8; u++) {
        float bv = d_bg[ocg * 8 + u];
        float r0 = fmaxf(fmaxf(acc[0][u], acc[1][u]), fmaxf(acc[4][u], acc[5][u])) + bv;
        float r1 = fmaxf(fmaxf(acc[2][u], acc[3][u]), fmaxf(acc[6][u], acc[7][u])) + bv;
        __half2 h = __floats2half2_rn(r0, r1);
        pk[u] = *(uint32_t*)&h;
    }
    uint32_t* gdst = d_g2 + ((size_t)b * 1152 + (m0 >> 1)) * 64 + ocg * 8;
    *(uint4*)(gdst)     = make_uint4(pk[0], pk[1], pk[2], pk[3]);
    *(uint4*)(gdst + 4) = make_uint4(pk[4], pk[5], pk[6], pk[7]);
}

// ----------------- K4: flash attention (unchanged from R12, 139us) -----------------
__global__ __launch_bounds__(128) void attn_tc() {
    extern __shared__ uint32_t smw[];
    int b = blockIdx.y;
    int n0 = blockIdx.x * 64;
    int tid = threadIdx.x;
    int w = tid >> 5, lane = tid & 31;
    int g = lane >> 2, tig = lane & 3;
    int qa = n0 + w * 16 + g, qb = qa + 8;

    uint32_t su = (uint32_t)__cvta_generic_to_shared(smw);
    uint32_t* P2w = smw + 13824;
    int lr = lane & 7, sel = lane >> 3;
    uint32_t koff = (uint32_t)(lr * 144 + (sel & 1) * 16 + ((sel >> 1) ? 9216 : 0));

    const uint4* phw4 = (const uint4*)d_phihi + (size_t)b * 2304 * 8;
    const uint4* plw4 = (const uint4*)d_philo + (size_t)b * 2304 * 8;
    const uint4* g4   = (const uint4*)d_g2 + (size_t)b * 1152 * 16;

    auto prefetch = [&](int m0, int buf) {
        uint32_t base = su + (uint32_t)buf * 27648u;
        #pragma unroll
        for (int t = 0; t < 4; t++) {
            int i = t * 128 + tid;
            int key = i >> 3, ch = i & 7;
            uint32_t d = (uint32_t)(key * 144 + ch * 16);
            cp16(base + d, phw4 + (size_t)(m0 + key) * 8 + ch);
            cp16(base + 9216 + d, plw4 + (size_t)(m0 + key) * 8 + ch);
        }
        #pragma unroll
        for (int t = 0; t < 4; t++) {
            int i = t * 128 + tid;
            int prow = i >> 4, c4 = i & 15;
            cp16(base + 18432 + (uint32_t)(prow * 288 + c4 * 16),
                 g4 + (size_t)((m0 >> 1) + prow) * 16 + c4);
        }
        cp_commit();
    };

    uint32_t Qhi[4][4], Qlo[4][4];
    {
        const uint32_t* qh = d_thQhi + (size_t)b * 9216 * 32;
        const uint32_t* ql = d_thQlo + (size_t)b * 9216 * 32;
        #pragma unroll
        for (int ks = 0; ks < 4; ks++) {
            Qhi[ks][0] = qh[(size_t)qa * 32 + ks * 8 + tig];
            Qhi[ks][1] = qh[(size_t)qb * 32 + ks * 8 + tig];
            Qhi[ks][2] = qh[(size_t)qa * 32 + ks * 8 + tig + 4];
            Qhi[ks][3] = qh[(size_t)qb * 32 + ks * 8 + tig + 4];
            Qlo[ks][0] = ql[(size_t)qa * 32 + ks * 8 + tig];
            Qlo[ks][1] = ql[(size_t)qb * 32 + ks * 8 + tig];
            Qlo[ks][2] = ql[(size_t)qa * 32 + ks * 8 + tig + 4];
            Qlo[ks][3] = ql[(size_t)qb * 32 + ks * 8 + tig + 4];
        }
    }
    float mA = -1e30f, mB = -1e30f, lA = 0.f, lB = 0.f;
    float O[8][4];
    #pragma unroll
    for (int nt = 0; nt < 8; nt++)
        #pragma unroll
        for (int u = 0; u < 4; u++) O[nt][u] = 0.f;

    prefetch(0, 0);

    for (int it = 0; it < 36; it++) {
        int buf = it & 1;
        if (it < 35) {
            prefetch((it + 1) * 64, buf ^ 1);
            asm volatile("cp.async.wait_group 1;");
        } else {
            asm volatile("cp.async.wait_group 0;");
        }
        __syncthreads();
        uint32_t kbase = su + (uint32_t)buf * 27648u;
        uint32_t* G2w = smw + buf * 6912 + 4608;

        float S[8][4];
        #pragma unroll
        for (int nt = 0; nt < 8; nt++) {
            S[nt][0] = 0.f; S[nt][1] = 0.f; S[nt][2] = 0.f; S[nt][3] = 0.f;
        }
        #pragma unroll
        for (int ks = 0; ks < 4; ks++) {
            #pragma unroll
            for (int nt = 0; nt < 8; nt++) {
                uint32_t kf[4];
                ldsm4(kf, kbase + (uint32_t)(nt * 1152 + ks * 32) + koff);
                mma_bf16(S[nt], Qhi[ks], kf[0], kf[1]);
                mma_bf16(S[nt], Qhi[ks], kf[2], kf[3]);
                mma_bf16(S[nt], Qlo[ks], kf[0], kf[1]);
            }
        }
        float mxA = -1e30f, mxB = -1e30f;
        #pragma unroll
        for (int nt = 0; nt < 8; nt++) {
            mxA = fmaxf(mxA, fmaxf(S[nt][0], S[nt][1]));
            mxB = fmaxf(mxB, fmaxf(S[nt][2], S[nt][3]));
        }
        mxA = fmaxf(mxA, __shfl_xor_sync(0xffffffffu, mxA, 1));
        mxA = fmaxf(mxA, __shfl_xor_sync(0xffffffffu, mxA, 2));
        mxB = fmaxf(mxB, __shfl_xor_sync(0xffffffffu, mxB, 1));
        mxB = fmaxf(mxB, __shfl_xor_sync(0xffffffffu, mxB, 2));
        float mnA = fmaxf(mA, mxA), mnB = fmaxf(mB, mxB);
        float aA = ex2f(mA - mnA), aB = ex2f(mB - mnB);
        mA = mnA; mB = mnB;
        float sumA = 0.f, sumB = 0.f;
        #pragma unroll
        for (int nt = 0; nt < 8; nt++) {
            S[nt][0] = ex2f(S[nt][0] - mA);
            S[nt][1] = ex2f(S[nt][1] - mA);
            S[nt][2] = ex2f(S[nt][2] - mB);
            S[nt][3] = ex2f(S[nt][3] - mB);
            sumA += S[nt][0] + S[nt][1];
            sumB += S[nt][2] + S[nt][3];
        }
        sumA += __shfl_xor_sync(0xffffffffu, sumA, 1);
        sumA += __shfl_xor_sync(0xffffffffu, sumA, 2);
        sumB += __shfl_xor_sync(0xffffffffu, sumB, 1);
        sumB += __shfl_xor_sync(0xffffffffu, sumB, 2);
        lA = lA * aA + sumA;
        lB = lB * aB + sumB;
        #pragma unroll
        for (int nt = 0; nt < 8; nt++) {
            O[nt][0] *= aA; O[nt][1] *= aA; O[nt][2] *= aB; O[nt][3] *= aB;
        }
        int q0 = w * 16 + g;
        #pragma unroll
        for (int nt = 0; nt < 8; nt++) {
            __half2 hA = __floats2half2_rn(S[nt][0], S[nt][1]);
            __half2 hB = __floats2half2_rn(S[nt][2], S[nt][3]);
            P2w[q0 * 36 + 4 * nt + tig]       = *(uint32_t*)&hA;
            P2w[(q0 + 8) * 36 + 4 * nt + tig] = *(uint32_t*)&hB;
        }
        __syncwarp();
        #pragma unroll
        for (int kt = 0; kt < 4; kt++) {
            uint32_t a[4];
            const uint32_t* PR = P2w + (w * 16 + g) * 36 + kt * 8 + tig;
            a[0] = PR[0];
            a[1] = PR[8 * 36];
            a[2] = PR[4];
            a[3] = PR[8 * 36 + 4];
            const uint32_t* GR = G2w + (kt * 8 + tig) * 72 + g;
            #pragma unroll
            for (int nt = 0; nt < 8; nt++) {
                uint32_t b0 = GR[nt * 8];
                uint32_t b1 = GR[4 * 72 + nt * 8];
                mma_fp16(O[nt], a, b0, b1);
            }
        }
        __syncthreads();
    }
    float* stage = (float*)smw;
    float ilA = 1.f / lA, ilB = 1.f / lB;
    int q0 = w * 16 + g;
    #pragma unroll
    for (int nt = 0; nt < 8; nt++) {
        int ch = nt * 8 + 2 * tig;
        stage[ch * 68 + q0]           = O[nt][0] * ilA;
        stage[(ch + 1) * 68 + q0]     = O[nt][1] * ilA;
        stage[ch * 68 + q0 + 8]       = O[nt][2] * ilB;
        stage[(ch + 1) * 68 + q0 + 8] = O[nt][3] * ilB;
    }
    __syncthreads();
    float* om = d_omap + (size_t)b * 64 * 9216 + n0;
    for (int i = tid; i < 1024; i += 128) {
        int ch = i >> 4, c4 = (i & 15) * 4;
        *(float4*)(om + (size_t)ch * 9216 + c4) = *(float4*)(stage + ch * 68 + c4);
    }
}

// ----------------- K5: fused (o_w o up) + bias + gamma*y (unchanged from R12) -----------------
__global__ __launch_bounds__(256) void out_k(const float* __restrict__ Y,
                                             const float* __restrict__ up_b,
                                             const float* __restrict__ gammap,
                                             float* __restrict__ out) {
    extern __shared__ float sm[];
    float* Os = sm;
    float* Ws = sm + 4096;
    int tc = blockIdx.x, tr = blockIdx.y;
    int b = blockIdx.z >> 2, ocb = blockIdx.z & 3;
    int tid = threadIdx.x;
    int og = tid & 15, pg = tid >> 4;
    for (int i = tid; i < 2048; i += 256) {
        int c2 = i >> 5, r4 = i & 31;
        ((float4*)Ws)[i] = *(const float4*)(d_W2 + c2 * 512 + ocb * 128 + r4 * 4);
    }
    for (int i = tid; i < 1024; i += 256) {
        int c2 = i >> 4, s4 = i & 15;
        int r = s4 >> 3, jc = (s4 & 7) * 4;
        ((float4*)Os)[i] = *(const float4*)(d_omap + ((size_t)b * 64 + c2) * 9216
                                            + (2 * tr + r) * 96 + tc * 32 + jc);
    }
    __syncthreads();
    float acc[4][8];
    #pragma unroll
    for (int i = 0; i < 4; i++)
        #pragma unroll
        for (int u = 0; u < 8; u++) acc[i][u] = 0.f;
    #pragma unroll 4
    for (int c2 = 0; c2 < 64; c2++) {
        const float* Ar = Os + c2 * 64;
        float2 a01 = *(const float2*)(Ar + 2 * pg);
        float2 a23 = *(const float2*)(Ar + 32 + 2 * pg);
        const float* Wr = Ws + c2 * 128 + og * 8;
        float4 w0 = *(const float4*)(Wr);
        float4 w1 = *(const float4*)(Wr + 4);
        float wv[8] = {w0.x, w0.y, w0.z, w0.w, w1.x, w1.y, w1.z, w1.w};
        #pragma unroll
        for (int u = 0; u < 8; u++) {
            acc[0][u] += a01.x * wv[u];
            acc[1][u] += a01.y * wv[u];
            acc[2][u] += a23.x * wv[u];
            acc[3][u] += a23.y * wv[u];
        }
    }
    __syncthreads();
    float* stg = Ws;
    #pragma unroll
    for (int u = 0; u < 8; u++) {
        int row = og * 8 + u;
        int oc_l = row >> 2, p = (row >> 1) & 1, q = row & 1;
        #pragma unroll
        for (int px = 0; px < 4; px++) {
            int r = px >> 1;
            int jc = 2 * pg + (px & 1);
            stg[oc_l * 256 + (2 * r + p) * 64 + 2 * jc + q] = acc[px][u];
        }
    }
    __syncthreads();
    float gamma = *gammap;
    for (int i = tid; i < 2048; i += 256) {
        int col4 = i & 15, lrow = (i >> 4) & 3, oc_l = i >> 6;
        int oc = ocb * 32 + oc_l;
        size_t gaddr = (((size_t)b * 128 + oc) * 192 + (4 * tr + lrow)) * 192 + tc * 64 + col4 * 4;
        float4 s = ((float4*)stg)[oc_l * 64 + lrow * 16 + col4];
        float4 yv = *(const float4*)(Y + gaddr);
        float bb = up_b[oc];
        float4 o = make_float4(s.x + bb + gamma * yv.x, s.y + bb + gamma * yv.y,
                               s.z + bb + gamma * yv.z, s.w + bb + gamma * yv.w);
        *(float4*)(out + gaddr) = o;
    }
}

// ----------------- launch -----------------
extern "C" void kernel_launch(void* const* d_in, const int* in_sizes, int n_in,
                              void* d_out, int out_size) {
    (void)in_sizes; (void)n_in; (void)out_size;
    const float* input_x = (const float*)d_in[0];
    const float* input_y = (const float*)d_in[1];
    const float* down0_w = (const float*)d_in[2];
    const float* down0_b = (const float*)d_in[3];
    const float* down1_w = (const float*)d_in[4];
    const float* down1_b = (const float*)d_in[5];
    const float* theta_w = (const float*)d_in[6];
    const float* phi_w   = (const float*)d_in[7];
    const float* g_w     = (const float*)d_in[8];
    const float* o_w     = (const float*)d_in[9];
    const float* up_w    = (const float*)d_in[10];
    const float* up_b    = (const float*)d_in[11];
    const float* gamma   = (const float*)d_in[12];
    float* out = (float*)d_out;

    cudaFuncSetAttribute(conv_tp, cudaFuncAttributeMaxDynamicSharedMemorySize, 67584);
    cudaFuncSetAttribute(attn_tc, cudaFuncAttributeMaxDynamicSharedMemorySize, 64512);
    cudaFuncSetAttribute(out_k, cudaFuncAttributeMaxDynamicSharedMemorySize, 49152);

    fuse_all<<<128, 256>>>(theta_w, phi_w, g_w, o_w,
                           down0_w, down0_b, down1_w, down1_b, up_w);
    conv_tp<<<dim3(3, 24, 4), 256, 67584>>>(input_x);
    conv_g<<<dim3(3, 24, 4), 128>>>(input_y);
    attn_tc<<<dim3(144, 4), 128, 64512>>>();
    out_k<<<dim3(3, 48, 16), 256, 49152>>>(input_y, up_b, gamma, out);
}

// round 14
// speedup vs baseline: 1.7819x; 1.0967x over previous
#include <cuda_runtime.h>
#include <cuda_bf16.h>
#include <cuda_fp16.h>
#include <cstdint>

#define SCALE_LOGIT 7.2134752044448169f   // TEMP(5) * log2(e)

// ----------------- device scratch (no allocation allowed) -----------------
__device__ __align__(16) uint32_t d_WtpH[256 * 128]; // [kpair][oc] bf16x2 hi (theta scaled | phi)
__device__ __align__(16) uint32_t d_WtpL[256 * 128]; // [kpair][oc] bf16x2 lo
__device__ __align__(16) float d_btp[128];
__device__ __align__(16) uint32_t d_WgH[256 * 64];   // [kpair][oc] bf16x2 hi
__device__ __align__(16) uint32_t d_WgL[256 * 64];   // [kpair][oc] bf16x2 lo
__device__ __align__(16) float d_bg[64];
__device__ __align__(16) float d_W2[64 * 512];
__device__ __align__(16) uint32_t d_thQhi[4 * 9216 * 32];  // [b][n][c/2] bf16x2 hi (scaled logits)
__device__ __align__(16) uint32_t d_thQlo[4 * 9216 * 32];  // [b][n][c/2] bf16x2 lo
__device__ __align__(16) unsigned short d_phihi[4 * 2304 * 64]; // [b][m][c] bf16 hi
__device__ __align__(16) unsigned short d_philo[4 * 2304 * 64]; // [b][m][c] bf16 lo
__device__ __align__(16) uint32_t d_g2[4 * 1152 * 64];    // [b][m/2][c] half2(g[2m],g[2m+1])
__device__ __align__(16) float d_omap[4 * 64 * 9216];     // [b][c][n]

__device__ __forceinline__ float ex2f(float x) {
    float r; asm("ex2.approx.f32 %0, %1;" : "=f"(r) : "f"(x)); return r;
}
__device__ __forceinline__ void mma_bf16(float* c, const uint32_t* a, uint32_t b0, uint32_t b1) {
    asm volatile("mma.sync.aligned.m16n8k16.row.col.f32.bf16.bf16.f32 "
                 "{%0,%1,%2,%3},{%4,%5,%6,%7},{%8,%9},{%0,%1,%2,%3};"
                 : "+f"(c[0]), "+f"(c[1]), "+f"(c[2]), "+f"(c[3])
                 : "r"(a[0]), "r"(a[1]), "r"(a[2]), "r"(a[3]), "r"(b0), "r"(b1));
}
__device__ __forceinline__ void mma_fp16(float* c, const uint32_t* a, uint32_t b0, uint32_t b1) {
    asm volatile("mma.sync.aligned.m16n8k16.row.col.f32.f16.f16.f32 "
                 "{%0,%1,%2,%3},{%4,%5,%6,%7},{%8,%9},{%0,%1,%2,%3};"
                 : "+f"(c[0]), "+f"(c[1]), "+f"(c[2]), "+f"(c[3])
                 : "r"(a[0]), "r"(a[1]), "r"(a[2]), "r"(a[3]), "r"(b0), "r"(b1));
}
__device__ __forceinline__ void ldsm4(uint32_t* r, uint32_t addr) {
    asm volatile("ldmatrix.sync.aligned.m8n8.x4.shared.b16 {%0,%1,%2,%3}, [%4];"
                 : "=r"(r[0]), "=r"(r[1]), "=r"(r[2]), "=r"(r[3]) : "r"(addr));
}
__device__ __forceinline__ uint32_t pack_bf16x2(unsigned short lo, unsigned short hi) {
    return (uint32_t)lo | ((uint32_t)hi << 16);
}
__device__ __forceinline__ uint32_t splitH(float a, float b, uint32_t& lo) {
    __nv_bfloat16 ha = __float2bfloat16_rn(a);
    __nv_bfloat16 hb = __float2bfloat16_rn(b);
    __nv_bfloat16 la = __float2bfloat16_rn(a - __bfloat162float(ha));
    __nv_bfloat16 lb = __float2bfloat16_rn(b - __bfloat162float(hb));
    lo = pack_bf16x2(__bfloat16_as_ushort(la), __bfloat16_as_ushort(lb));
    return pack_bf16x2(__bfloat16_as_ushort(ha), __bfloat16_as_ushort(hb));
}
__device__ __forceinline__ void cp16(uint32_t dst, const void* src) {
    asm volatile("cp.async.cg.shared.global [%0], [%1], 16;" :: "r"(dst), "l"(src));
}
__device__ __forceinline__ void cp_commit() { asm volatile("cp.async.commit_group;"); }

// ----------------- K1: all weight fusions in ONE launch -----------------
// grid 128 x 256: blocks [0,64) theta/phi, [64,96) g (split pair layout), [96,128) W2
__global__ void fuse_all(const float* __restrict__ theta_w, const float* __restrict__ phi_w,
                         const float* __restrict__ g_w, const float* __restrict__ o_w,
                         const float* __restrict__ down0_w, const float* __restrict__ down0_b,
                         const float* __restrict__ down1_w, const float* __restrict__ down1_b,
                         const float* __restrict__ up_w) {
    int blk = blockIdx.x;
    int tid = threadIdx.x;
    if (blk < 64) {
        int idx = blk * 256 + tid;
        int oc = idx & 127, ic = idx >> 7;
        const float* wrow = (oc < 64) ? (theta_w + oc * 128) : (phi_w + (oc - 64) * 128);
        float a0 = 0.f, a1 = 0.f, a2 = 0.f, a3 = 0.f, ab = 0.f;
        for (int c = 0; c < 128; c++) {
            float wv = wrow[c];
            float4 dv = *(const float4*)(down0_w + (size_t)(c * 128 + ic) * 4);
            a0 += wv * dv.x; a1 += wv * dv.y; a2 += wv * dv.z; a3 += wv * dv.w;
            if (ic == 0) ab += wv * down0_b[c];
        }
        float s = (oc < 64) ? SCALE_LOGIT : 1.f;
        uint32_t l0, l1;
        uint32_t h0 = splitH(a0 * s, a1 * s, l0);
        uint32_t h1 = splitH(a2 * s, a3 * s, l1);
        d_WtpH[(ic * 2 + 0) * 128 + oc] = h0;
        d_WtpL[(ic * 2 + 0) * 128 + oc] = l0;
        d_WtpH[(ic * 2 + 1) * 128 + oc] = h1;
        d_WtpL[(ic * 2 + 1) * 128 + oc] = l1;
        if (ic == 0) d_btp[oc] = ab * s;
    } else if (blk < 96) {
        int idx = (blk - 64) * 256 + tid;
        int oc = idx & 63, ic = idx >> 6;
        const float* wrow = g_w + oc * 128;
        float a0 = 0.f, a1 = 0.f, a2 = 0.f, a3 = 0.f, ab = 0.f;
        for (int c = 0; c < 128; c++) {
            float wv = wrow[c];
            float4 dv = *(const float4*)(down1_w + (size_t)(c * 128 + ic) * 4);
            a0 += wv * dv.x; a1 += wv * dv.y; a2 += wv * dv.z; a3 += wv * dv.w;
            if (ic == 0) ab += wv * down1_b[c];
        }
        uint32_t l0, l1;
        uint32_t h0 = splitH(a0, a1, l0);
        uint32_t h1 = splitH(a2, a3, l1);
        d_WgH[(ic * 2 + 0) * 64 + oc] = h0;
        d_WgL[(ic * 2 + 0) * 64 + oc] = l0;
        d_WgH[(ic * 2 + 1) * 64 + oc] = h1;
        d_WgL[(ic * 2 + 1) * 64 + oc] = l1;
        if (ic == 0) d_bg[oc] = ab;
    } else {
        int idx = (blk - 96) * 256 + tid;
        int c2 = idx & 63, oc = idx >> 6;
        float a0 = 0.f, a1 = 0.f, a2 = 0.f, a3 = 0.f;
        for (int och = 0; och < 128; och++) {
            float wv = o_w[och * 64 + c2];
            float4 dv = *(const float4*)(up_w + (size_t)(och * 128 + oc) * 4);
            a0 += wv * dv.x; a1 += wv * dv.y; a2 += wv * dv.z; a3 += wv * dv.w;
        }
        d_W2[c2 * 512 + oc * 4 + 0] = a0;
        d_W2[c2 * 512 + oc * 4 + 1] = a1;
        d_W2[c2 * 512 + oc * 4 + 2] = a2;
        d_W2[c2 * 512 + oc * 4 + 3] = a3;
    }
}

// ----------------- K2: theta+phi conv via split-bf16 tensor cores (unchanged from R13) -----------------
// grid (3, 24, 4), 256 threads. Out tile: 128 oc x 128 px, K=512. dyn smem 67584 B.
__global__ __launch_bounds__(256) void conv_tp(const float* __restrict__ X) {
    extern __shared__ uint32_t smw[];
    int b = blockIdx.z, tr = blockIdx.y, tc = blockIdx.x;
    int tid = threadIdx.x;
    int w = tid >> 5, lane = tid & 31;
    int g = lane >> 2, tig = lane & 3;
    int w16 = w * 16;
    const float* Xb = X + (size_t)b * 128 * 192 * 192;
    uint32_t su = (uint32_t)__cvta_generic_to_shared(smw);

    float acc[16][4];
    #pragma unroll
    for (int nt = 0; nt < 16; nt++)
        #pragma unroll
        for (int u = 0; u < 4; u++) acc[nt][u] = 0.f;

    auto issueW = [&](int icb, int buf) {
        uint32_t base = su + (uint32_t)buf * 33792u;
        #pragma unroll
        for (int t = 0; t < 2; t++) {
            int i = t * 256 + tid;
            int row = i >> 5, seg = i & 31;
            cp16(base + (uint32_t)(row * 528 + seg * 16),
                 d_WtpH + (size_t)(icb * 16 + row) * 128 + seg * 4);
            cp16(base + 8448u + (uint32_t)(row * 528 + seg * 16),
                 d_WtpL + (size_t)(icb * 16 + row) * 128 + seg * 4);
        }
        cp_commit();
    };
    float2 xr[8];
    auto loadX = [&](int icb) {
        #pragma unroll
        for (int t = 0; t < 8; t++) {
            int i = t * 256 + tid;
            int jc = i & 31, ro = (i >> 5) & 3, p = (i >> 7) & 1, lic = i >> 8;
            xr[t] = ((const float2*)(Xb + ((size_t)(icb * 8 + lic) * 192
                       + 8 * tr + 2 * ro + p) * 192 + tc * 64))[jc];
        }
    };
    auto stsX = [&](int buf) {
        uint32_t* XH = smw + buf * 8448 + 4224;
        uint32_t* XL = XH + 2112;
        #pragma unroll
        for (int t = 0; t < 8; t++) {
            int i = t * 256 + tid;
            int jc = i & 31, ro = (i >> 5) & 3, p = (i >> 7) & 1, lic = i >> 8;
            int kk = lic * 2 + p, px = ro * 32 + jc;
            uint32_t lo;
            uint32_t hi = splitH(xr[t].x, xr[t].y, lo);
            XH[kk * 132 + px] = hi;
            XL[kk * 132 + px] = lo;
        }
    };

    issueW(0, 0);
    loadX(0);
    asm volatile("cp.async.wait_group 0;");
    stsX(0);
    __syncthreads();

    for (int icb = 0; icb < 16; icb++) {
        int buf = icb & 1;
        if (icb < 15) { issueW(icb + 1, buf ^ 1); loadX(icb + 1); }
        const uint32_t* WH = smw + buf * 8448;
        const uint32_t* WL = WH + 2112;
        const uint32_t* XH = WH + 4224;
        const uint32_t* XL = WH + 6336;
        #pragma unroll
        for (int ks = 0; ks < 2; ks++) {
            uint32_t ah[4], al[4];
            const uint32_t* W0 = WH + (ks * 8 + tig) * 132;
            const uint32_t* W1 = WH + (ks * 8 + 4 + tig) * 132;
            ah[0] = W0[w16 + g]; ah[1] = W0[w16 + g + 8];
            ah[2] = W1[w16 + g]; ah[3] = W1[w16 + g + 8];
            const uint32_t* V0 = WL + (ks * 8 + tig) * 132;
            const uint32_t* V1 = WL + (ks * 8 + 4 + tig) * 132;
            al[0] = V0[w16 + g]; al[1] = V0[w16 + g + 8];
            al[2] = V1[w16 + g]; al[3] = V1[w16 + g + 8];
            const uint32_t* B0 = XH + (ks * 8 + tig) * 132 + g;
            const uint32_t* B1 = XH + (ks * 8 + 4 + tig) * 132 + g;
            const uint32_t* C0 = XL + (ks * 8 + tig) * 132 + g;
            const uint32_t* C1 = XL + (ks * 8 + 4 + tig) * 132 + g;
            #pragma unroll
            for (int nt = 0; nt < 16; nt++) {
                uint32_t bh0 = B0[nt * 8], bh1 = B1[nt * 8];
                uint32_t bl0 = C0[nt * 8], bl1 = C1[nt * 8];
                mma_bf16(acc[nt], ah, bh0, bh1);
                mma_bf16(acc[nt], ah, bl0, bl1);
                mma_bf16(acc[nt], al, bh0, bh1);
            }
        }
        if (icb < 15) {
            __syncthreads();
            stsX(buf ^ 1);
            asm volatile("cp.async.wait_group 0;");
            __syncthreads();
        }
    }
    __syncthreads();
    float* Cs = (float*)smw;
    #pragma unroll
    for (int nt = 0; nt < 16; nt++) {
        int col = nt * 8 + 2 * tig;
        Cs[(w16 + g) * 132 + col]       = acc[nt][0];
        Cs[(w16 + g) * 132 + col + 1]   = acc[nt][1];
        Cs[(w16 + g + 8) * 132 + col]     = acc[nt][2];
        Cs[(w16 + g + 8) * 132 + col + 1] = acc[nt][3];
    }
    __syncthreads();
    {
        uint32_t* qh = d_thQhi + (size_t)b * 9216 * 32;
        uint32_t* ql = d_thQlo + (size_t)b * 9216 * 32;
        #pragma unroll
        for (int j = 0; j < 16; j++) {
            int idx = j * 256 + tid;
            int px = idx & 127, wd = idx >> 7;
            int c0 = 2 * wd;
            float v0 = Cs[c0 * 132 + px] + d_btp[c0];
            float v1 = Cs[(c0 + 1) * 132 + px] + d_btp[c0 + 1];
            int ro = px >> 5, jc = px & 31;
            int n = (4 * tr + ro) * 96 + tc * 32 + jc;
            uint32_t lo;
            uint32_t hi = splitH(v0, v1, lo);
            qh[(size_t)n * 32 + wd] = hi;
            ql[(size_t)n * 32 + wd] = lo;
        }
    }
    {
        #pragma unroll
        for (int j = 0; j < 8; j++) {
            int idx = j * 256 + tid;
            int c = idx & 63, pm = idx >> 6;
            int rp = pm >> 4, cqp = pm & 15;
            const float* Cr = Cs + (64 + c) * 132 + (2 * rp) * 32 + 2 * cqp;
            float v = fmaxf(fmaxf(Cr[0], Cr[1]), fmaxf(Cr[32], Cr[33])) + d_btp[64 + c];
            int m = (2 * tr + rp) * 48 + tc * 16 + cqp;
            __nv_bfloat16 h = __float2bfloat16_rn(v);
            __nv_bfloat16 l = __float2bfloat16_rn(v - __bfloat162float(h));
            size_t a0 = ((size_t)b * 2304 + m) * 64 + c;
            d_phihi[a0] = __bfloat16_as_ushort(h);
            d_philo[a0] = __bfloat16_as_ushort(l);
        }
    }
}

// ----------------- K3: g conv via split-bf16 tensor cores + maxpool -----------------
// grid (3, 24, 4), 256 threads. Out tile: 64 oc x 128 px, K=512.
// dyn smem 51200 B: per buffer (stride 6400 words): WH@0 (16x68), WL@1088, XH@2176 (16x132), XL@4288.
// Epilogue: Cs[64][132] fp32 (8448 words).
__global__ __launch_bounds__(256) void conv_g(const float* __restrict__ Y) {
    extern __shared__ uint32_t smw[];
    int b = blockIdx.z, tr = blockIdx.y, tc = blockIdx.x;
    int tid = threadIdx.x;
    int w = tid >> 5, lane = tid & 31;
    int g = lane >> 2, tig = lane & 3;
    int mt = w & 3, nh = w >> 2;
    int m16 = mt * 16, n64 = nh * 64;
    const float* Yb = Y + (size_t)b * 128 * 192 * 192;
    uint32_t su = (uint32_t)__cvta_generic_to_shared(smw);

    float acc[8][4];
    #pragma unroll
    for (int nt = 0; nt < 8; nt++)
        #pragma unroll
        for (int u = 0; u < 4; u++) acc[nt][u] = 0.f;

    auto issueW = [&](int icb, int buf) {
        uint32_t base = su + (uint32_t)buf * 25600u;
        int row = tid >> 4, seg = tid & 15;
        cp16(base + (uint32_t)(row * 272 + seg * 16),
             d_WgH + (size_t)(icb * 16 + row) * 64 + seg * 4);
        cp16(base + 4352u + (uint32_t)(row * 272 + seg * 16),
             d_WgL + (size_t)(icb * 16 + row) * 64 + seg * 4);
        cp_commit();
    };
    float2 xr[8];
    auto loadX = [&](int icb) {
        #pragma unroll
        for (int t = 0; t < 8; t++) {
            int i = t * 256 + tid;
            int jc = i & 31, ro = (i >> 5) & 3, p = (i >> 7) & 1, lic = i >> 8;
            xr[t] = ((const float2*)(Yb + ((size_t)(icb * 8 + lic) * 192
                       + 8 * tr + 2 * ro + p) * 192 + tc * 64))[jc];
        }
    };
    auto stsX = [&](int buf) {
        uint32_t* XH = smw + buf * 6400 + 2176;
        uint32_t* XL = XH + 2112;
        #pragma unroll
        for (int t = 0; t < 8; t++) {
            int i = t * 256 + tid;
            int jc = i & 31, ro = (i >> 5) & 3, p = (i >> 7) & 1, lic = i >> 8;
            int kk = lic * 2 + p, px = ro * 32 + jc;
            uint32_t lo;
            uint32_t hi = splitH(xr[t].x, xr[t].y, lo);
            XH[kk * 132 + px] = hi;
            XL[kk * 132 + px] = lo;
        }
    };

    issueW(0, 0);
    loadX(0);
    asm volatile("cp.async.wait_group 0;");
    stsX(0);
    __syncthreads();

    for (int icb = 0; icb < 16; icb++) {
        int buf = icb & 1;
        if (icb < 15) { issueW(icb + 1, buf ^ 1); loadX(icb + 1); }
        const uint32_t* WH = smw + buf * 6400;
        const uint32_t* WL = WH + 1088;
        const uint32_t* XH = WH + 2176;
        const uint32_t* XL = WH + 4288;
        #pragma unroll
        for (int ks = 0; ks < 2; ks++) {
            uint32_t ah[4], al[4];
            const uint32_t* W0 = WH + (ks * 8 + tig) * 68;
            const uint32_t* W1 = WH + (ks * 8 + 4 + tig) * 68;
            ah[0] = W0[m16 + g]; ah[1] = W0[m16 + g + 8];
            ah[2] = W1[m16 + g]; ah[3] = W1[m16 + g + 8];
            const uint32_t* V0 = WL + (ks * 8 + tig) * 68;
            const uint32_t* V1 = WL + (ks * 8 + 4 + tig) * 68;
            al[0] = V0[m16 + g]; al[1] = V0[m16 + g + 8];
            al[2] = V1[m16 + g]; al[3] = V1[m16 + g + 8];
            const uint32_t* B0 = XH + (ks * 8 + tig) * 132 + n64 + g;
            const uint32_t* B1 = XH + (ks * 8 + 4 + tig) * 132 + n64 + g;
            const uint32_t* C0 = XL + (ks * 8 + tig) * 132 + n64 + g;
            const uint32_t* C1 = XL + (ks * 8 + 4 + tig) * 132 + n64 + g;
            #pragma unroll
            for (int nt = 0; nt < 8; nt++) {
                uint32_t bh0 = B0[nt * 8], bh1 = B1[nt * 8];
                uint32_t bl0 = C0[nt * 8], bl1 = C1[nt * 8];
                mma_bf16(acc[nt], ah, bh0, bh1);
                mma_bf16(acc[nt], ah, bl0, bl1);
                mma_bf16(acc[nt], al, bh0, bh1);
            }
        }
        if (icb < 15) {
            __syncthreads();
            stsX(buf ^ 1);
            asm volatile("cp.async.wait_group 0;");
            __syncthreads();
        }
    }
    __syncthreads();
    float* Cs = (float*)smw;    // [64 oc][132]
    #pragma unroll
    for (int nt = 0; nt < 8; nt++) {
        int col = n64 + nt * 8 + 2 * tig;
        Cs[(m16 + g) * 132 + col]       = acc[nt][0];
        Cs[(m16 + g) * 132 + col + 1]   = acc[nt][1];
        Cs[(m16 + g + 8) * 132 + col]     = acc[nt][2];
        Cs[(m16 + g + 8) * 132 + col + 1] = acc[nt][3];
    }
    __syncthreads();
    // maxpool 2x2 + bias -> fp16 key-pair store (32 keys x 64 ch = 1024 half2 words)
    #pragma unroll
    for (int j = 0; j < 4; j++) {
        int i = j * 256 + tid;
        int c = i & 63, pp = i >> 6;
        int rp = pp >> 3, cq = pp & 7;
        const float* Cr = Cs + c * 132 + (2 * rp) * 32 + 4 * cq;
        float bv = d_bg[c];
        float v0 = fmaxf(fmaxf(Cr[0], Cr[1]), fmaxf(Cr[32], Cr[33])) + bv;
        float v1 = fmaxf(fmaxf(Cr[2], Cr[3]), fmaxf(Cr[34], Cr[35])) + bv;
        int m0 = (2 * tr + rp) * 48 + tc * 16 + 2 * cq;
        __half2 h = __floats2half2_rn(v0, v1);
        d_g2[((size_t)b * 1152 + (m0 >> 1)) * 64 + c] = *(uint32_t*)&h;
    }
}

// ----------------- K4: flash attention (unchanged from R12/R13, 138us) -----------------
__global__ __launch_bounds__(128) void attn_tc() {
    extern __shared__ uint32_t smw[];
    int b = blockIdx.y;
    int n0 = blockIdx.x * 64;
    int tid = threadIdx.x;
    int w = tid >> 5, lane = tid & 31;
    int g = lane >> 2, tig = lane & 3;
    int qa = n0 + w * 16 + g, qb = qa + 8;

    uint32_t su = (uint32_t)__cvta_generic_to_shared(smw);
    uint32_t* P2w = smw + 13824;
    int lr = lane & 7, sel = lane >> 3;
    uint32_t koff = (uint32_t)(lr * 144 + (sel & 1) * 16 + ((sel >> 1) ? 9216 : 0));

    const uint4* phw4 = (const uint4*)d_phihi + (size_t)b * 2304 * 8;
    const uint4* plw4 = (const uint4*)d_philo + (size_t)b * 2304 * 8;
    const uint4* g4   = (const uint4*)d_g2 + (size_t)b * 1152 * 16;

    auto prefetch = [&](int m0, int buf) {
        uint32_t base = su + (uint32_t)buf * 27648u;
        #pragma unroll
        for (int t = 0; t < 4; t++) {
            int i = t * 128 + tid;
            int key = i >> 3, ch = i & 7;
            uint32_t d = (uint32_t)(key * 144 + ch * 16);
            cp16(base + d, phw4 + (size_t)(m0 + key) * 8 + ch);
            cp16(base + 9216 + d, plw4 + (size_t)(m0 + key) * 8 + ch);
        }
        #pragma unroll
        for (int t = 0; t < 4; t++) {
            int i = t * 128 + tid;
            int prow = i >> 4, c4 = i & 15;
            cp16(base + 18432 + (uint32_t)(prow * 288 + c4 * 16),
                 g4 + (size_t)((m0 >> 1) + prow) * 16 + c4);
        }
        cp_commit();
    };

    uint32_t Qhi[4][4], Qlo[4][4];
    {
        const uint32_t* qh = d_thQhi + (size_t)b * 9216 * 32;
        const uint32_t* ql = d_thQlo + (size_t)b * 9216 * 32;
        #pragma unroll
        for (int ks = 0; ks < 4; ks++) {
            Qhi[ks][0] = qh[(size_t)qa * 32 + ks * 8 + tig];
            Qhi[ks][1] = qh[(size_t)qb * 32 + ks * 8 + tig];
            Qhi[ks][2] = qh[(size_t)qa * 32 + ks * 8 + tig + 4];
            Qhi[ks][3] = qh[(size_t)qb * 32 + ks * 8 + tig + 4];
            Qlo[ks][0] = ql[(size_t)qa * 32 + ks * 8 + tig];
            Qlo[ks][1] = ql[(size_t)qb * 32 + ks * 8 + tig];
            Qlo[ks][2] = ql[(size_t)qa * 32 + ks * 8 + tig + 4];
            Qlo[ks][3] = ql[(size_t)qb * 32 + ks * 8 + tig + 4];
        }
    }
    float mA = -1e30f, mB = -1e30f, lA = 0.f, lB = 0.f;
    float O[8][4];
    #pragma unroll
    for (int nt = 0; nt < 8; nt++)
        #pragma unroll
        for (int u = 0; u < 4; u++) O[nt][u] = 0.f;

    prefetch(0, 0);

    for (int it = 0; it < 36; it++) {
        int buf = it & 1;
        if (it < 35) {
            prefetch((it + 1) * 64, buf ^ 1);
            asm volatile("cp.async.wait_group 1;");
        } else {
            asm volatile("cp.async.wait_group 0;");
        }
        __syncthreads();
        uint32_t kbase = su + (uint32_t)buf * 27648u;
        uint32_t* G2w = smw + buf * 6912 + 4608;

        float S[8][4];
        #pragma unroll
        for (int nt = 0; nt < 8; nt++) {
            S[nt][0] = 0.f; S[nt][1] = 0.f; S[nt][2] = 0.f; S[nt][3] = 0.f;
        }
        #pragma unroll
        for (int ks = 0; ks < 4; ks++) {
            #pragma unroll
            for (int nt = 0; nt < 8; nt++) {
                uint32_t kf[4];
                ldsm4(kf, kbase + (uint32_t)(nt * 1152 + ks * 32) + koff);
                mma_bf16(S[nt], Qhi[ks], kf[0], kf[1]);
                mma_bf16(S[nt], Qhi[ks], kf[2], kf[3]);
                mma_bf16(S[nt], Qlo[ks], kf[0], kf[1]);
            }
        }
        float mxA = -1e30f, mxB = -1e30f;
        #pragma unroll
        for (int nt = 0; nt < 8; nt++) {
            mxA = fmaxf(mxA, fmaxf(S[nt][0], S[nt][1]));
            mxB = fmaxf(mxB, fmaxf(S[nt][2], S[nt][3]));
        }
        mxA = fmaxf(mxA, __shfl_xor_sync(0xffffffffu, mxA, 1));
        mxA = fmaxf(mxA, __shfl_xor_sync(0xffffffffu, mxA, 2));
        mxB = fmaxf(mxB, __shfl_xor_sync(0xffffffffu, mxB, 1));
        mxB = fmaxf(mxB, __shfl_xor_sync(0xffffffffu, mxB, 2));
        float mnA = fmaxf(mA, mxA), mnB = fmaxf(mB, mxB);
        float aA = ex2f(mA - mnA), aB = ex2f(mB - mnB);
        mA = mnA; mB = mnB;
        float sumA = 0.f, sumB = 0.f;
        #pragma unroll
        for (int nt = 0; nt < 8; nt++) {
            S[nt][0] = ex2f(S[nt][0] - mA);
            S[nt][1] = ex2f(S[nt][1] - mA);
            S[nt][2] = ex2f(S[nt][2] - mB);
            S[nt][3] = ex2f(S[nt][3] - mB);
            sumA += S[nt][0] + S[nt][1];
            sumB += S[nt][2] + S[nt][3];
        }
        sumA += __shfl_xor_sync(0xffffffffu, sumA, 1);
        sumA += __shfl_xor_sync(0xffffffffu, sumA, 2);
        sumB += __shfl_xor_sync(0xffffffffu, sumB, 1);
        sumB += __shfl_xor_sync(0xffffffffu, sumB, 2);
        lA = lA * aA + sumA;
        lB = lB * aB + sumB;
        #pragma unroll
        for (int nt = 0; nt < 8; nt++) {
            O[nt][0] *= aA; O[nt][1] *= aA; O[nt][2] *= aB; O[nt][3] *= aB;
        }
        int q0 = w * 16 + g;
        #pragma unroll
        for (int nt = 0; nt < 8; nt++) {
            __half2 hA = __floats2half2_rn(S[nt][0], S[nt][1]);
            __half2 hB = __floats2half2_rn(S[nt][2], S[nt][3]);
            P2w[q0 * 36 + 4 * nt + tig]       = *(uint32_t*)&hA;
            P2w[(q0 + 8) * 36 + 4 * nt + tig] = *(uint32_t*)&hB;
        }
        __syncwarp();
        #pragma unroll
        for (int kt = 0; kt < 4; kt++) {
            uint32_t a[4];
            const uint32_t* PR = P2w + (w * 16 + g) * 36 + kt * 8 + tig;
            a[0] = PR[0];
            a[1] = PR[8 * 36];
            a[2] = PR[4];
            a[3] = PR[8 * 36 + 4];
            const uint32_t* GR = G2w + (kt * 8 + tig) * 72 + g;
            #pragma unroll
            for (int nt = 0; nt < 8; nt++) {
                uint32_t b0 = GR[nt * 8];
                uint32_t b1 = GR[4 * 72 + nt * 8];
                mma_fp16(O[nt], a, b0, b1);
            }
        }
        __syncthreads();
    }
    float* stage = (float*)smw;
    float ilA = 1.f / lA, ilB = 1.f / lB;
    int q0 = w * 16 + g;
    #pragma unroll
    for (int nt = 0; nt < 8; nt++) {
        int ch = nt * 8 + 2 * tig;
        stage[ch * 68 + q0]           = O[nt][0] * ilA;
        stage[(ch + 1) * 68 + q0]     = O[nt][1] * ilA;
        stage[ch * 68 + q0 + 8]       = O[nt][2] * ilB;
        stage[(ch + 1) * 68 + q0 + 8] = O[nt][3] * ilB;
    }
    __syncthreads();
    float* om = d_omap + (size_t)b * 64 * 9216 + n0;
    for (int i = tid; i < 1024; i += 128) {
        int ch = i >> 4, c4 = (i & 15) * 4;
        *(float4*)(om + (size_t)ch * 9216 + c4) = *(float4*)(stage + ch * 68 + c4);
    }
}

// ----------------- K5: fused (o_w o up) + bias + gamma*y (unchanged) -----------------
__global__ __launch_bounds__(256) void out_k(const float* __restrict__ Y,
                                             const float* __restrict__ up_b,
                                             const float* __restrict__ gammap,
                                             float* __restrict__ out) {
    extern __shared__ float sm[];
    float* Os = sm;
    float* Ws = sm + 4096;
    int tc = blockIdx.x, tr = blockIdx.y;
    int b = blockIdx.z >> 2, ocb = blockIdx.z & 3;
    int tid = threadIdx.x;
    int og = tid & 15, pg = tid >> 4;
    for (int i = tid; i < 2048; i += 256) {
        int c2 = i >> 5, r4 = i & 31;
        ((float4*)Ws)[i] = *(const float4*)(d_W2 + c2 * 512 + ocb * 128 + r4 * 4);
    }
    for (int i = tid; i < 1024; i += 256) {
        int c2 = i >> 4, s4 = i & 15;
        int r = s4 >> 3, jc = (s4 & 7) * 4;
        ((float4*)Os)[i] = *(const float4*)(d_omap + ((size_t)b * 64 + c2) * 9216
                                            + (2 * tr + r) * 96 + tc * 32 + jc);
    }
    __syncthreads();
    float acc[4][8];
    #pragma unroll
    for (int i = 0; i < 4; i++)
        #pragma unroll
        for (int u = 0; u < 8; u++) acc[i][u] = 0.f;
    #pragma unroll 4
    for (int c2 = 0; c2 < 64; c2++) {
        const float* Ar = Os + c2 * 64;
        float2 a01 = *(const float2*)(Ar + 2 * pg);
        float2 a23 = *(const float2*)(Ar + 32 + 2 * pg);
        const float* Wr = Ws + c2 * 128 + og * 8;
        float4 w0 = *(const float4*)(Wr);
        float4 w1 = *(const float4*)(Wr + 4);
        float wv[8] = {w0.x, w0.y, w0.z, w0.w, w1.x, w1.y, w1.z, w1.w};
        #pragma unroll
        for (int u = 0; u < 8; u++) {
            acc[0][u] += a01.x * wv[u];
            acc[1][u] += a01.y * wv[u];
            acc[2][u] += a23.x * wv[u];
            acc[3][u] += a23.y * wv[u];
        }
    }
    __syncthreads();
    float* stg = Ws;
    #pragma unroll
    for (int u = 0; u < 8; u++) {
        int row = og * 8 + u;
        int oc_l = row >> 2, p = (row >> 1) & 1, q = row & 1;
        #pragma unroll
        for (int px = 0; px < 4; px++) {
            int r = px >> 1;
            int jc = 2 * pg + (px & 1);
            stg[oc_l * 256 + (2 * r + p) * 64 + 2 * jc + q] = acc[px][u];
        }
    }
    __syncthreads();
    float gamma = *gammap;
    for (int i = tid; i < 2048; i += 256) {
        int col4 = i & 15, lrow = (i >> 4) & 3, oc_l = i >> 6;
        int oc = ocb * 32 + oc_l;
        size_t gaddr = (((size_t)b * 128 + oc) * 192 + (4 * tr + lrow)) * 192 + tc * 64 + col4 * 4;
        float4 s = ((float4*)stg)[oc_l * 64 + lrow * 16 + col4];
        float4 yv = *(const float4*)(Y + gaddr);
        float bb = up_b[oc];
        float4 o = make_float4(s.x + bb + gamma * yv.x, s.y + bb + gamma * yv.y,
                               s.z + bb + gamma * yv.z, s.w + bb + gamma * yv.w);
        *(float4*)(out + gaddr) = o;
    }
}

// ----------------- launch -----------------
extern "C" void kernel_launch(void* const* d_in, const int* in_sizes, int n_in,
                              void* d_out, int out_size) {
    (void)in_sizes; (void)n_in; (void)out_size;
    const float* input_x = (const float*)d_in[0];
    const float* input_y = (const float*)d_in[1];
    const float* down0_w = (const float*)d_in[2];
    const float* down0_b = (const float*)d_in[3];
    const float* down1_w = (const float*)d_in[4];
    const float* down1_b = (const float*)d_in[5];
    const float* theta_w = (const float*)d_in[6];
    const float* phi_w   = (const float*)d_in[7];
    const float* g_w     = (const float*)d_in[8];
    const float* o_w     = (const float*)d_in[9];
    const float* up_w    = (const float*)d_in[10];
    const float* up_b    = (const float*)d_in[11];
    const float* gamma   = (const float*)d_in[12];
    float* out = (float*)d_out;

    cudaFuncSetAttribute(conv_tp, cudaFuncAttributeMaxDynamicSharedMemorySize, 67584);
    cudaFuncSetAttribute(conv_g, cudaFuncAttributeMaxDynamicSharedMemorySize, 51200);
    cudaFuncSetAttribute(attn_tc, cudaFuncAttributeMaxDynamicSharedMemorySize, 64512);
    cudaFuncSetAttribute(out_k, cudaFuncAttributeMaxDynamicSharedMemorySize, 49152);

    fuse_all<<<128, 256>>>(theta_w, phi_w, g_w, o_w,
                           down0_w, down0_b, down1_w, down1_b, up_w);
    conv_tp<<<dim3(3, 24, 4), 256, 67584>>>(input_x);
    conv_g<<<dim3(3, 24, 4), 256, 51200>>>(input_y);
    attn_tc<<<dim3(144, 4), 128, 64512>>>();
    out_k<<<dim3(3, 48, 16), 256, 49152>>>(input_y, up_b, gamma, out);
}

// round 15
// speedup vs baseline: 2.2449x; 1.2598x over previous
#include <cuda_runtime.h>
#include <cuda_bf16.h>
#include <cuda_fp16.h>
#include <cstdint>

#define SCALE_LOGIT 7.2134752044448169f   // TEMP(5) * log2(e)

// ----------------- device scratch (no allocation allowed) -----------------
__device__ __align__(16) uint32_t d_WtpH[256 * 128]; // [kpair][oc] bf16x2 hi (theta scaled | phi)
__device__ __align__(16) uint32_t d_WtpL[256 * 128]; // [kpair][oc] bf16x2 lo
__device__ __align__(16) float d_btp[128];
__device__ __align__(16) uint32_t d_WgH[256 * 64];   // [kpair][oc] bf16x2 hi
__device__ __align__(16) uint32_t d_WgL[256 * 64];   // [kpair][oc] bf16x2 lo
__device__ __align__(16) float d_bg[64];
__device__ __align__(16) uint32_t d_W2H[32 * 512];   // [c2pair][orow=oc*4+p*2+q] bf16x2 hi
__device__ __align__(16) uint32_t d_W2L[32 * 512];   // [c2pair][orow] bf16x2 lo
__device__ __align__(16) uint32_t d_thQhi[4 * 9216 * 32];  // [b][n][c/2] bf16x2 hi (scaled logits)
__device__ __align__(16) uint32_t d_thQlo[4 * 9216 * 32];  // [b][n][c/2] bf16x2 lo
__device__ __align__(16) unsigned short d_phihi[4 * 2304 * 64]; // [b][m][c] bf16 hi
__device__ __align__(16) unsigned short d_philo[4 * 2304 * 64]; // [b][m][c] bf16 lo
__device__ __align__(16) uint32_t d_g2[4 * 1152 * 64];    // [b][m/2][c] half2(g[2m],g[2m+1])
__device__ __align__(16) float d_omap[4 * 64 * 9216];     // [b][c][n]

__device__ __forceinline__ float ex2f(float x) {
    float r; asm("ex2.approx.f32 %0, %1;" : "=f"(r) : "f"(x)); return r;
}
__device__ __forceinline__ void mma_bf16(float* c, const uint32_t* a, uint32_t b0, uint32_t b1) {
    asm volatile("mma.sync.aligned.m16n8k16.row.col.f32.bf16.bf16.f32 "
                 "{%0,%1,%2,%3},{%4,%5,%6,%7},{%8,%9},{%0,%1,%2,%3};"
                 : "+f"(c[0]), "+f"(c[1]), "+f"(c[2]), "+f"(c[3])
                 : "r"(a[0]), "r"(a[1]), "r"(a[2]), "r"(a[3]), "r"(b0), "r"(b1));
}
__device__ __forceinline__ void mma_fp16(float* c, const uint32_t* a, uint32_t b0, uint32_t b1) {
    asm volatile("mma.sync.aligned.m16n8k16.row.col.f32.f16.f16.f32 "
                 "{%0,%1,%2,%3},{%4,%5,%6,%7},{%8,%9},{%0,%1,%2,%3};"
                 : "+f"(c[0]), "+f"(c[1]), "+f"(c[2]), "+f"(c[3])
                 : "r"(a[0]), "r"(a[1]), "r"(a[2]), "r"(a[3]), "r"(b0), "r"(b1));
}
__device__ __forceinline__ void ldsm4(uint32_t* r, uint32_t addr) {
    asm volatile("ldmatrix.sync.aligned.m8n8.x4.shared.b16 {%0,%1,%2,%3}, [%4];"
                 : "=r"(r[0]), "=r"(r[1]), "=r"(r[2]), "=r"(r[3]) : "r"(addr));
}
__device__ __forceinline__ uint32_t pack_bf16x2(unsigned short lo, unsigned short hi) {
    return (uint32_t)lo | ((uint32_t)hi << 16);
}
__device__ __forceinline__ uint32_t splitH(float a, float b, uint32_t& lo) {
    __nv_bfloat16 ha = __float2bfloat16_rn(a);
    __nv_bfloat16 hb = __float2bfloat16_rn(b);
    __nv_bfloat16 la = __float2bfloat16_rn(a - __bfloat162float(ha));
    __nv_bfloat16 lb = __float2bfloat16_rn(b - __bfloat162float(hb));
    lo = pack_bf16x2(__bfloat16_as_ushort(la), __bfloat16_as_ushort(lb));
    return pack_bf16x2(__bfloat16_as_ushort(ha), __bfloat16_as_ushort(hb));
}
__device__ __forceinline__ void cp16(uint32_t dst, const void* src) {
    asm volatile("cp.async.cg.shared.global [%0], [%1], 16;" :: "r"(dst), "l"(src));
}
__device__ __forceinline__ void cp_commit() { asm volatile("cp.async.commit_group;"); }

// ----------------- K1: all weight fusions in ONE launch -----------------
// grid 128 x 256: [0,64) theta/phi split pairs, [64,96) g split pairs, [96,128) W2 split pairs
__global__ void fuse_all(const float* __restrict__ theta_w, const float* __restrict__ phi_w,
                         const float* __restrict__ g_w, const float* __restrict__ o_w,
                         const float* __restrict__ down0_w, const float* __restrict__ down0_b,
                         const float* __restrict__ down1_w, const float* __restrict__ down1_b,
                         const float* __restrict__ up_w) {
    int blk = blockIdx.x;
    int tid = threadIdx.x;
    if (blk < 64) {
        int idx = blk * 256 + tid;
        int oc = idx & 127, ic = idx >> 7;
        const float* wrow = (oc < 64) ? (theta_w + oc * 128) : (phi_w + (oc - 64) * 128);
        float a0 = 0.f, a1 = 0.f, a2 = 0.f, a3 = 0.f, ab = 0.f;
        for (int c = 0; c < 128; c++) {
            float wv = wrow[c];
            float4 dv = *(const float4*)(down0_w + (size_t)(c * 128 + ic) * 4);
            a0 += wv * dv.x; a1 += wv * dv.y; a2 += wv * dv.z; a3 += wv * dv.w;
            if (ic == 0) ab += wv * down0_b[c];
        }
        float s = (oc < 64) ? SCALE_LOGIT : 1.f;
        uint32_t l0, l1;
        uint32_t h0 = splitH(a0 * s, a1 * s, l0);
        uint32_t h1 = splitH(a2 * s, a3 * s, l1);
        d_WtpH[(ic * 2 + 0) * 128 + oc] = h0;
        d_WtpL[(ic * 2 + 0) * 128 + oc] = l0;
        d_WtpH[(ic * 2 + 1) * 128 + oc] = h1;
        d_WtpL[(ic * 2 + 1) * 128 + oc] = l1;
        if (ic == 0) d_btp[oc] = ab * s;
    } else if (blk < 96) {
        int idx = (blk - 64) * 256 + tid;
        int oc = idx & 63, ic = idx >> 6;
        const float* wrow = g_w + oc * 128;
        float a0 = 0.f, a1 = 0.f, a2 = 0.f, a3 = 0.f, ab = 0.f;
        for (int c = 0; c < 128; c++) {
            float wv = wrow[c];
            float4 dv = *(const float4*)(down1_w + (size_t)(c * 128 + ic) * 4);
            a0 += wv * dv.x; a1 += wv * dv.y; a2 += wv * dv.z; a3 += wv * dv.w;
            if (ic == 0) ab += wv * down1_b[c];
        }
        uint32_t l0, l1;
        uint32_t h0 = splitH(a0, a1, l0);
        uint32_t h1 = splitH(a2, a3, l1);
        d_WgH[(ic * 2 + 0) * 64 + oc] = h0;
        d_WgL[(ic * 2 + 0) * 64 + oc] = l0;
        d_WgH[(ic * 2 + 1) * 64 + oc] = h1;
        d_WgL[(ic * 2 + 1) * 64 + oc] = l1;
        if (ic == 0) d_bg[oc] = ab;
    } else {
        int idx = (blk - 96) * 256 + tid;
        int c2 = idx & 63, oc = idx >> 6;
        float a0 = 0.f, a1 = 0.f, a2 = 0.f, a3 = 0.f;
        for (int och = 0; och < 128; och++) {
            float wv = o_w[och * 64 + c2];
            float4 dv = *(const float4*)(up_w + (size_t)(och * 128 + oc) * 4);
            a0 += wv * dv.x; a1 += wv * dv.y; a2 += wv * dv.z; a3 += wv * dv.w;
        }
        // pair c2 (even) with c2+1 (odd) via lane-parity shfl; c2&1 == lane&1
        float p0 = __shfl_xor_sync(0xffffffffu, a0, 1);
        float p1 = __shfl_xor_sync(0xffffffffu, a1, 1);
        float p2 = __shfl_xor_sync(0xffffffffu, a2, 1);
        float p3 = __shfl_xor_sync(0xffffffffu, a3, 1);
        if (!(c2 & 1)) {
            int kp = c2 >> 1;
            uint32_t lo, hi;
            hi = splitH(a0, p0, lo);
            d_W2H[kp * 512 + oc * 4 + 0] = hi; d_W2L[kp * 512 + oc * 4 + 0] = lo;
            hi = splitH(a1, p1, lo);
            d_W2H[kp * 512 + oc * 4 + 1] = hi; d_W2L[kp * 512 + oc * 4 + 1] = lo;
            hi = splitH(a2, p2, lo);
            d_W2H[kp * 512 + oc * 4 + 2] = hi; d_W2L[kp * 512 + oc * 4 + 2] = lo;
            hi = splitH(a3, p3, lo);
            d_W2H[kp * 512 + oc * 4 + 3] = hi; d_W2L[kp * 512 + oc * 4 + 3] = lo;
        }
    }
}

// ----------------- K2: theta+phi conv via split-bf16 tensor cores (unchanged) -----------------
__global__ __launch_bounds__(256) void conv_tp(const float* __restrict__ X) {
    extern __shared__ uint32_t smw[];
    int b = blockIdx.z, tr = blockIdx.y, tc = blockIdx.x;
    int tid = threadIdx.x;
    int w = tid >> 5, lane = tid & 31;
    int g = lane >> 2, tig = lane & 3;
    int w16 = w * 16;
    const float* Xb = X + (size_t)b * 128 * 192 * 192;
    uint32_t su = (uint32_t)__cvta_generic_to_shared(smw);

    float acc[16][4];
    #pragma unroll
    for (int nt = 0; nt < 16; nt++)
        #pragma unroll
        for (int u = 0; u < 4; u++) acc[nt][u] = 0.f;

    auto issueW = [&](int icb, int buf) {
        uint32_t base = su + (uint32_t)buf * 33792u;
        #pragma unroll
        for (int t = 0; t < 2; t++) {
            int i = t * 256 + tid;
            int row = i >> 5, seg = i & 31;
            cp16(base + (uint32_t)(row * 528 + seg * 16),
                 d_WtpH + (size_t)(icb * 16 + row) * 128 + seg * 4);
            cp16(base + 8448u + (uint32_t)(row * 528 + seg * 16),
                 d_WtpL + (size_t)(icb * 16 + row) * 128 + seg * 4);
        }
        cp_commit();
    };
    float2 xr[8];
    auto loadX = [&](int icb) {
        #pragma unroll
        for (int t = 0; t < 8; t++) {
            int i = t * 256 + tid;
            int jc = i & 31, ro = (i >> 5) & 3, p = (i >> 7) & 1, lic = i >> 8;
            xr[t] = ((const float2*)(Xb + ((size_t)(icb * 8 + lic) * 192
                       + 8 * tr + 2 * ro + p) * 192 + tc * 64))[jc];
        }
    };
    auto stsX = [&](int buf) {
        uint32_t* XH = smw + buf * 8448 + 4224;
        uint32_t* XL = XH + 2112;
        #pragma unroll
        for (int t = 0; t < 8; t++) {
            int i = t * 256 + tid;
            int jc = i & 31, ro = (i >> 5) & 3, p = (i >> 7) & 1, lic = i >> 8;
            int kk = lic * 2 + p, px = ro * 32 + jc;
            uint32_t lo;
            uint32_t hi = splitH(xr[t].x, xr[t].y, lo);
            XH[kk * 132 + px] = hi;
            XL[kk * 132 + px] = lo;
        }
    };

    issueW(0, 0);
    loadX(0);
    asm volatile("cp.async.wait_group 0;");
    stsX(0);
    __syncthreads();

    for (int icb = 0; icb < 16; icb++) {
        int buf = icb & 1;
        if (icb < 15) { issueW(icb + 1, buf ^ 1); loadX(icb + 1); }
        const uint32_t* WH = smw + buf * 8448;
        const uint32_t* WL = WH + 2112;
        const uint32_t* XH = WH + 4224;
        const uint32_t* XL = WH + 6336;
        #pragma unroll
        for (int ks = 0; ks < 2; ks++) {
            uint32_t ah[4], al[4];
            const uint32_t* W0 = WH + (ks * 8 + tig) * 132;
            const uint32_t* W1 = WH + (ks * 8 + 4 + tig) * 132;
            ah[0] = W0[w16 + g]; ah[1] = W0[w16 + g + 8];
            ah[2] = W1[w16 + g]; ah[3] = W1[w16 + g + 8];
            const uint32_t* V0 = WL + (ks * 8 + tig) * 132;
            const uint32_t* V1 = WL + (ks * 8 + 4 + tig) * 132;
            al[0] = V0[w16 + g]; al[1] = V0[w16 + g + 8];
            al[2] = V1[w16 + g]; al[3] = V1[w16 + g + 8];
            const uint32_t* B0 = XH + (ks * 8 + tig) * 132 + g;
            const uint32_t* B1 = XH + (ks * 8 + 4 + tig) * 132 + g;
            const uint32_t* C0 = XL + (ks * 8 + tig) * 132 + g;
            const uint32_t* C1 = XL + (ks * 8 + 4 + tig) * 132 + g;
            #pragma unroll
            for (int nt = 0; nt < 16; nt++) {
                uint32_t bh0 = B0[nt * 8], bh1 = B1[nt * 8];
                uint32_t bl0 = C0[nt * 8], bl1 = C1[nt * 8];
                mma_bf16(acc[nt], ah, bh0, bh1);
                mma_bf16(acc[nt], ah, bl0, bl1);
                mma_bf16(acc[nt], al, bh0, bh1);
            }
        }
        if (icb < 15) {
            __syncthreads();
            stsX(buf ^ 1);
            asm volatile("cp.async.wait_group 0;");
            __syncthreads();
        }
    }
    __syncthreads();
    float* Cs = (float*)smw;
    #pragma unroll
    for (int nt = 0; nt < 16; nt++) {
        int col = nt * 8 + 2 * tig;
        Cs[(w16 + g) * 132 + col]       = acc[nt][0];
        Cs[(w16 + g) * 132 + col + 1]   = acc[nt][1];
        Cs[(w16 + g + 8) * 132 + col]     = acc[nt][2];
        Cs[(w16 + g + 8) * 132 + col + 1] = acc[nt][3];
    }
    __syncthreads();
    {
        uint32_t* qh = d_thQhi + (size_t)b * 9216 * 32;
        uint32_t* ql = d_thQlo + (size_t)b * 9216 * 32;
        #pragma unroll
        for (int j = 0; j < 16; j++) {
            int idx = j * 256 + tid;
            int px = idx & 127, wd = idx >> 7;
            int c0 = 2 * wd;
            float v0 = Cs[c0 * 132 + px] + d_btp[c0];
            float v1 = Cs[(c0 + 1) * 132 + px] + d_btp[c0 + 1];
            int ro = px >> 5, jc = px & 31;
            int n = (4 * tr + ro) * 96 + tc * 32 + jc;
            uint32_t lo;
            uint32_t hi = splitH(v0, v1, lo);
            qh[(size_t)n * 32 + wd] = hi;
            ql[(size_t)n * 32 + wd] = lo;
        }
    }
    {
        #pragma unroll
        for (int j = 0; j < 8; j++) {
            int idx = j * 256 + tid;
            int c = idx & 63, pm = idx >> 6;
            int rp = pm >> 4, cqp = pm & 15;
            const float* Cr = Cs + (64 + c) * 132 + (2 * rp) * 32 + 2 * cqp;
            float v = fmaxf(fmaxf(Cr[0], Cr[1]), fmaxf(Cr[32], Cr[33])) + d_btp[64 + c];
            int m = (2 * tr + rp) * 48 + tc * 16 + cqp;
            __nv_bfloat16 h = __float2bfloat16_rn(v);
            __nv_bfloat16 l = __float2bfloat16_rn(v - __bfloat162float(h));
            size_t a0 = ((size_t)b * 2304 + m) * 64 + c;
            d_phihi[a0] = __bfloat16_as_ushort(h);
            d_philo[a0] = __bfloat16_as_ushort(l);
        }
    }
}

// ----------------- K3: g conv via split-bf16 tensor cores + maxpool (unchanged) -----------------
__global__ __launch_bounds__(256) void conv_g(const float* __restrict__ Y) {
    extern __shared__ uint32_t smw[];
    int b = blockIdx.z, tr = blockIdx.y, tc = blockIdx.x;
    int tid = threadIdx.x;
    int w = tid >> 5, lane = tid & 31;
    int g = lane >> 2, tig = lane & 3;
    int mt = w & 3, nh = w >> 2;
    int m16 = mt * 16, n64 = nh * 64;
    const float* Yb = Y + (size_t)b * 128 * 192 * 192;
    uint32_t su = (uint32_t)__cvta_generic_to_shared(smw);

    float acc[8][4];
    #pragma unroll
    for (int nt = 0; nt < 8; nt++)
        #pragma unroll
        for (int u = 0; u < 4; u++) acc[nt][u] = 0.f;

    auto issueW = [&](int icb, int buf) {
        uint32_t base = su + (uint32_t)buf * 25600u;
        int row = tid >> 4, seg = tid & 15;
        cp16(base + (uint32_t)(row * 272 + seg * 16),
             d_WgH + (size_t)(icb * 16 + row) * 64 + seg * 4);
        cp16(base + 4352u + (uint32_t)(row * 272 + seg * 16),
             d_WgL + (size_t)(icb * 16 + row) * 64 + seg * 4);
        cp_commit();
    };
    float2 xr[8];
    auto loadX = [&](int icb) {
        #pragma unroll
        for (int t = 0; t < 8; t++) {
            int i = t * 256 + tid;
            int jc = i & 31, ro = (i >> 5) & 3, p = (i >> 7) & 1, lic = i >> 8;
            xr[t] = ((const float2*)(Yb + ((size_t)(icb * 8 + lic) * 192
                       + 8 * tr + 2 * ro + p) * 192 + tc * 64))[jc];
        }
    };
    auto stsX = [&](int buf) {
        uint32_t* XH = smw + buf * 6400 + 2176;
        uint32_t* XL = XH + 2112;
        #pragma unroll
        for (int t = 0; t < 8; t++) {
            int i = t * 256 + tid;
            int jc = i & 31, ro = (i >> 5) & 3, p = (i >> 7) & 1, lic = i >> 8;
            int kk = lic * 2 + p, px = ro * 32 + jc;
            uint32_t lo;
            uint32_t hi = splitH(xr[t].x, xr[t].y, lo);
            XH[kk * 132 + px] = hi;
            XL[kk * 132 + px] = lo;
        }
    };

    issueW(0, 0);
    loadX(0);
    asm volatile("cp.async.wait_group 0;");
    stsX(0);
    __syncthreads();

    for (int icb = 0; icb < 16; icb++) {
        int buf = icb & 1;
        if (icb < 15) { issueW(icb + 1, buf ^ 1); loadX(icb + 1); }
        const uint32_t* WH = smw + buf * 6400;
        const uint32_t* WL = WH + 1088;
        const uint32_t* XH = WH + 2176;
        const uint32_t* XL = WH + 4288;
        #pragma unroll
        for (int ks = 0; ks < 2; ks++) {
            uint32_t ah[4], al[4];
            const uint32_t* W0 = WH + (ks * 8 + tig) * 68;
            const uint32_t* W1 = WH + (ks * 8 + 4 + tig) * 68;
            ah[0] = W0[m16 + g]; ah[1] = W0[m16 + g + 8];
            ah[2] = W1[m16 + g]; ah[3] = W1[m16 + g + 8];
            const uint32_t* V0 = WL + (ks * 8 + tig) * 68;
            const uint32_t* V1 = WL + (ks * 8 + 4 + tig) * 68;
            al[0] = V0[m16 + g]; al[1] = V0[m16 + g + 8];
            al[2] = V1[m16 + g]; al[3] = V1[m16 + g + 8];
            const uint32_t* B0 = XH + (ks * 8 + tig) * 132 + n64 + g;
            const uint32_t* B1 = XH + (ks * 8 + 4 + tig) * 132 + n64 + g;
            const uint32_t* C0 = XL + (ks * 8 + tig) * 132 + n64 + g;
            const uint32_t* C1 = XL + (ks * 8 + 4 + tig) * 132 + n64 + g;
            #pragma unroll
            for (int nt = 0; nt < 8; nt++) {
                uint32_t bh0 = B0[nt * 8], bh1 = B1[nt * 8];
                uint32_t bl0 = C0[nt * 8], bl1 = C1[nt * 8];
                mma_bf16(acc[nt], ah, bh0, bh1);
                mma_bf16(acc[nt], ah, bl0, bl1);
                mma_bf16(acc[nt], al, bh0, bh1);
            }
        }
        if (icb < 15) {
            __syncthreads();
            stsX(buf ^ 1);
            asm volatile("cp.async.wait_group 0;");
            __syncthreads();
        }
    }
    __syncthreads();
    float* Cs = (float*)smw;
    #pragma unroll
    for (int nt = 0; nt < 8; nt++) {
        int col = n64 + nt * 8 + 2 * tig;
        Cs[(m16 + g) * 132 + col]       = acc[nt][0];
        Cs[(m16 + g) * 132 + col + 1]   = acc[nt][1];
        Cs[(m16 + g + 8) * 132 + col]     = acc[nt][2];
        Cs[(m16 + g + 8) * 132 + col + 1] = acc[nt][3];
    }
    __syncthreads();
    #pragma unroll
    for (int j = 0; j < 4; j++) {
        int i = j * 256 + tid;
        int c = i & 63, pp = i >> 6;
        int rp = pp >> 3, cq = pp & 7;
        const float* Cr = Cs + c * 132 + (2 * rp) * 32 + 4 * cq;
        float bv = d_bg[c];
        float v0 = fmaxf(fmaxf(Cr[0], Cr[1]), fmaxf(Cr[32], Cr[33])) + bv;
        float v1 = fmaxf(fmaxf(Cr[2], Cr[3]), fmaxf(Cr[34], Cr[35])) + bv;
        int m0 = (2 * tr + rp) * 48 + tc * 16 + 2 * cq;
        __half2 h = __floats2half2_rn(v0, v1);
        d_g2[((size_t)b * 1152 + (m0 >> 1)) * 64 + c] = *(uint32_t*)&h;
    }
}

// ----------------- K4: flash attention (unchanged, 138us) -----------------
__global__ __launch_bounds__(128) void attn_tc() {
    extern __shared__ uint32_t smw[];
    int b = blockIdx.y;
    int n0 = blockIdx.x * 64;
    int tid = threadIdx.x;
    int w = tid >> 5, lane = tid & 31;
    int g = lane >> 2, tig = lane & 3;
    int qa = n0 + w * 16 + g, qb = qa + 8;

    uint32_t su = (uint32_t)__cvta_generic_to_shared(smw);
    uint32_t* P2w = smw + 13824;
    int lr = lane & 7, sel = lane >> 3;
    uint32_t koff = (uint32_t)(lr * 144 + (sel & 1) * 16 + ((sel >> 1) ? 9216 : 0));

    const uint4* phw4 = (const uint4*)d_phihi + (size_t)b * 2304 * 8;
    const uint4* plw4 = (const uint4*)d_philo + (size_t)b * 2304 * 8;
    const uint4* g4   = (const uint4*)d_g2 + (size_t)b * 1152 * 16;

    auto prefetch = [&](int m0, int buf) {
        uint32_t base = su + (uint32_t)buf * 27648u;
        #pragma unroll
        for (int t = 0; t < 4; t++) {
            int i = t * 128 + tid;
            int key = i >> 3, ch = i & 7;
            uint32_t d = (uint32_t)(key * 144 + ch * 16);
            cp16(base + d, phw4 + (size_t)(m0 + key) * 8 + ch);
            cp16(base + 9216 + d, plw4 + (size_t)(m0 + key) * 8 + ch);
        }
        #pragma unroll
        for (int t = 0; t < 4; t++) {
            int i = t * 128 + tid;
            int prow = i >> 4, c4 = i & 15;
            cp16(base + 18432 + (uint32_t)(prow * 288 + c4 * 16),
                 g4 + (size_t)((m0 >> 1) + prow) * 16 + c4);
        }
        cp_commit();
    };

    uint32_t Qhi[4][4], Qlo[4][4];
    {
        const uint32_t* qh = d_thQhi + (size_t)b * 9216 * 32;
        const uint32_t* ql = d_thQlo + (size_t)b * 9216 * 32;
        #pragma unroll
        for (int ks = 0; ks < 4; ks++) {
            Qhi[ks][0] = qh[(size_t)qa * 32 + ks * 8 + tig];
            Qhi[ks][1] = qh[(size_t)qb * 32 + ks * 8 + tig];
            Qhi[ks][2] = qh[(size_t)qa * 32 + ks * 8 + tig + 4];
            Qhi[ks][3] = qh[(size_t)qb * 32 + ks * 8 + tig + 4];
            Qlo[ks][0] = ql[(size_t)qa * 32 + ks * 8 + tig];
            Qlo[ks][1] = ql[(size_t)qb * 32 + ks * 8 + tig];
            Qlo[ks][2] = ql[(size_t)qa * 32 + ks * 8 + tig + 4];
            Qlo[ks][3] = ql[(size_t)qb * 32 + ks * 8 + tig + 4];
        }
    }
    float mA = -1e30f, mB = -1e30f, lA = 0.f, lB = 0.f;
    float O[8][4];
    #pragma unroll
    for (int nt = 0; nt < 8; nt++)
        #pragma unroll
        for (int u = 0; u < 4; u++) O[nt][u] = 0.f;

    prefetch(0, 0);

    for (int it = 0; it < 36; it++) {
        int buf = it & 1;
        if (it < 35) {
            prefetch((it + 1) * 64, buf ^ 1);
            asm volatile("cp.async.wait_group 1;");
        } else {
            asm volatile("cp.async.wait_group 0;");
        }
        __syncthreads();
        uint32_t kbase = su + (uint32_t)buf * 27648u;
        uint32_t* G2w = smw + buf * 6912 + 4608;

        float S[8][4];
        #pragma unroll
        for (int nt = 0; nt < 8; nt++) {
            S[nt][0] = 0.f; S[nt][1] = 0.f; S[nt][2] = 0.f; S[nt][3] = 0.f;
        }
        #pragma unroll
        for (int ks = 0; ks < 4; ks++) {
            #pragma unroll
            for (int nt = 0; nt < 8; nt++) {
                uint32_t kf[4];
                ldsm4(kf, kbase + (uint32_t)(nt * 1152 + ks * 32) + koff);
                mma_bf16(S[nt], Qhi[ks], kf[0], kf[1]);
                mma_bf16(S[nt], Qhi[ks], kf[2], kf[3]);
                mma_bf16(S[nt], Qlo[ks], kf[0], kf[1]);
            }
        }
        float mxA = -1e30f, mxB = -1e30f;
        #pragma unroll
        for (int nt = 0; nt < 8; nt++) {
            mxA = fmaxf(mxA, fmaxf(S[nt][0], S[nt][1]));
            mxB = fmaxf(mxB, fmaxf(S[nt][2], S[nt][3]));
        }
        mxA = fmaxf(mxA, __shfl_xor_sync(0xffffffffu, mxA, 1));
        mxA = fmaxf(mxA, __shfl_xor_sync(0xffffffffu, mxA, 2));
        mxB = fmaxf(mxB, __shfl_xor_sync(0xffffffffu, mxB, 1));
        mxB = fmaxf(mxB, __shfl_xor_sync(0xffffffffu, mxB, 2));
        float mnA = fmaxf(mA, mxA), mnB = fmaxf(mB, mxB);
        float aA = ex2f(mA - mnA), aB = ex2f(mB - mnB);
        mA = mnA; mB = mnB;
        float sumA = 0.f, sumB = 0.f;
        #pragma unroll
        for (int nt = 0; nt < 8; nt++) {
            S[nt][0] = ex2f(S[nt][0] - mA);
            S[nt][1] = ex2f(S[nt][1] - mA);
            S[nt][2] = ex2f(S[nt][2] - mB);
            S[nt][3] = ex2f(S[nt][3] - mB);
            sumA += S[nt][0] + S[nt][1];
            sumB += S[nt][2] + S[nt][3];
        }
        sumA += __shfl_xor_sync(0xffffffffu, sumA, 1);
        sumA += __shfl_xor_sync(0xffffffffu, sumA, 2);
        sumB += __shfl_xor_sync(0xffffffffu, sumB, 1);
        sumB += __shfl_xor_sync(0xffffffffu, sumB, 2);
        lA = lA * aA + sumA;
        lB = lB * aB + sumB;
        #pragma unroll
        for (int nt = 0; nt < 8; nt++) {
            O[nt][0] *= aA; O[nt][1] *= aA; O[nt][2] *= aB; O[nt][3] *= aB;
        }
        int q0 = w * 16 + g;
        #pragma unroll
        for (int nt = 0; nt < 8; nt++) {
            __half2 hA = __floats2half2_rn(S[nt][0], S[nt][1]);
            __half2 hB = __floats2half2_rn(S[nt][2], S[nt][3]);
            P2w[q0 * 36 + 4 * nt + tig]       = *(uint32_t*)&hA;
            P2w[(q0 + 8) * 36 + 4 * nt + tig] = *(uint32_t*)&hB;
        }
        __syncwarp();
        #pragma unroll
        for (int kt = 0; kt < 4; kt++) {
            uint32_t a[4];
            const uint32_t* PR = P2w + (w * 16 + g) * 36 + kt * 8 + tig;
            a[0] = PR[0];
            a[1] = PR[8 * 36];
            a[2] = PR[4];
            a[3] = PR[8 * 36 + 4];
            const uint32_t* GR = G2w + (kt * 8 + tig) * 72 + g;
            #pragma unroll
            for (int nt = 0; nt < 8; nt++) {
                uint32_t b0 = GR[nt * 8];
                uint32_t b1 = GR[4 * 72 + nt * 8];
                mma_fp16(O[nt], a, b0, b1);
            }
        }
        __syncthreads();
    }
    float* stage = (float*)smw;
    float ilA = 1.f / lA, ilB = 1.f / lB;
    int q0 = w * 16 + g;
    #pragma unroll
    for (int nt = 0; nt < 8; nt++) {
        int ch = nt * 8 + 2 * tig;
        stage[ch * 68 + q0]           = O[nt][0] * ilA;
        stage[(ch + 1) * 68 + q0]     = O[nt][1] * ilA;
        stage[ch * 68 + q0 + 8]       = O[nt][2] * ilB;
        stage[(ch + 1) * 68 + q0 + 8] = O[nt][3] * ilB;
    }
    __syncthreads();
    float* om = d_omap + (size_t)b * 64 * 9216 + n0;
    for (int i = tid; i < 1024; i += 128) {
        int ch = i >> 4, c4 = (i & 15) * 4;
        *(float4*)(om + (size_t)ch * 9216 + c4) = *(float4*)(stage + ch * 68 + c4);
    }
}

// ----------------- K5: output GEMM via split-bf16 tensor cores + bias + gamma*y -----------------
// grid (3, 24, 16): z = b*4 + ocb. Tile: 128 px (M) x 128 orow (N), K=64.
// dyn smem 67584 B (16896 words): AH@0 (32x132), AL@4224, BH@8448, BL@12672; epilogue Cs[128][132] reuses all.
__global__ __launch_bounds__(256) void out_k(const float* __restrict__ Y,
                                             const float* __restrict__ up_b,
                                             const float* __restrict__ gammap,
                                             float* __restrict__ out) {
    extern __shared__ uint32_t smw[];
    int tc = blockIdx.x, tr = blockIdx.y;
    int b = blockIdx.z >> 2, ocb = blockIdx.z & 3;
    int tid = threadIdx.x;
    int w = tid >> 5, lane = tid & 31;
    int g = lane >> 2, tig = lane & 3;
    int w16 = w * 16;
    uint32_t su = (uint32_t)__cvta_generic_to_shared(smw);
    uint32_t* AH = smw;
    uint32_t* AL = smw + 4224;

    // W2 tiles via cp.async (32 kpair x 128 orow, hi+lo)
    #pragma unroll
    for (int t = 0; t < 4; t++) {
        int i = t * 256 + tid;
        int kp = i >> 5, seg = i & 31;
        cp16(su + 33792u + (uint32_t)(kp * 528 + seg * 16),
             d_W2H + (size_t)kp * 512 + ocb * 128 + seg * 4);
        cp16(su + 50688u + (uint32_t)(kp * 528 + seg * 16),
             d_W2L + (size_t)kp * 512 + ocb * 128 + seg * 4);
    }
    cp_commit();

    // omap tile: pack c2-pairs, split hi/lo
    const float* om = d_omap + (size_t)b * 64 * 9216;
    #pragma unroll
    for (int t = 0; t < 4; t++) {
        int unit = t * 256 + tid;       // 1024 units: kp x px4
        int kp = unit >> 5, p4 = unit & 31;
        int ro = p4 >> 3, jc4 = (p4 & 7) * 4;
        int n = (4 * tr + ro) * 96 + tc * 32 + jc4;
        float4 r0 = *(const float4*)(om + (size_t)(2 * kp) * 9216 + n);
        float4 r1 = *(const float4*)(om + (size_t)(2 * kp + 1) * 9216 + n);
        int px = ro * 32 + jc4;
        uint32_t lo, hi;
        hi = splitH(r0.x, r1.x, lo); AH[kp * 132 + px] = hi;     AL[kp * 132 + px] = lo;
        hi = splitH(r0.y, r1.y, lo); AH[kp * 132 + px + 1] = hi; AL[kp * 132 + px + 1] = lo;
        hi = splitH(r0.z, r1.z, lo); AH[kp * 132 + px + 2] = hi; AL[kp * 132 + px + 2] = lo;
        hi = splitH(r0.w, r1.w, lo); AH[kp * 132 + px + 3] = hi; AL[kp * 132 + px + 3] = lo;
    }
    asm volatile("cp.async.wait_group 0;");
    __syncthreads();

    float acc[16][4];
    #pragma unroll
    for (int nt = 0; nt < 16; nt++)
        #pragma unroll
        for (int u = 0; u < 4; u++) acc[nt][u] = 0.f;

    const uint32_t* BH = smw + 8448;
    const uint32_t* BL = smw + 12672;
    #pragma unroll
    for (int ks = 0; ks < 4; ks++) {
        uint32_t ah[4], al[4];
        const uint32_t* A0 = AH + (ks * 8 + tig) * 132;
        const uint32_t* A1 = AH + (ks * 8 + 4 + tig) * 132;
        ah[0] = A0[w16 + g]; ah[1] = A0[w16 + g + 8];
        ah[2] = A1[w16 + g]; ah[3] = A1[w16 + g + 8];
        const uint32_t* L0 = AL + (ks * 8 + tig) * 132;
        const uint32_t* L1 = AL + (ks * 8 + 4 + tig) * 132;
        al[0] = L0[w16 + g]; al[1] = L0[w16 + g + 8];
        al[2] = L1[w16 + g]; al[3] = L1[w16 + g + 8];
        const uint32_t* B0 = BH + (ks * 8 + tig) * 132 + g;
        const uint32_t* B1 = BH + (ks * 8 + 4 + tig) * 132 + g;
        const uint32_t* C0 = BL + (ks * 8 + tig) * 132 + g;
        const uint32_t* C1 = BL + (ks * 8 + 4 + tig) * 132 + g;
        #pragma unroll
        for (int nt = 0; nt < 16; nt++) {
            uint32_t bh0 = B0[nt * 8], bh1 = B1[nt * 8];
            uint32_t bl0 = C0[nt * 8], bl1 = C1[nt * 8];
            mma_bf16(acc[nt], ah, bh0, bh1);
            mma_bf16(acc[nt], ah, bl0, bl1);
            mma_bf16(acc[nt], al, bh0, bh1);
        }
    }
    __syncthreads();
    // stage C[orow][px]
    float* Cs = (float*)smw;
    #pragma unroll
    for (int nt = 0; nt < 16; nt++) {
        int col = nt * 8 + 2 * tig;
        Cs[col * 132 + w16 + g]           = acc[nt][0];
        Cs[(col + 1) * 132 + w16 + g]     = acc[nt][1];
        Cs[col * 132 + w16 + g + 8]       = acc[nt][2];
        Cs[(col + 1) * 132 + w16 + g + 8] = acc[nt][3];
    }
    __syncthreads();
    float gamma = *gammap;
    #pragma unroll
    for (int j = 0; j < 16; j++) {
        int i = j * 256 + tid;           // 4096 float4
        int col4 = i & 15, lrow = (i >> 4) & 7, oc_l = i >> 7;
        int ro = lrow >> 1, p = lrow & 1;
        int base0 = (oc_l * 4 + p * 2) * 132 + ro * 32 + 2 * col4;
        float4 s;
        s.x = Cs[base0];
        s.y = Cs[base0 + 132];
        s.z = Cs[base0 + 1];
        s.w = Cs[base0 + 133];
        int oc = ocb * 32 + oc_l;
        size_t gaddr = (((size_t)b * 128 + oc) * 192 + (8 * tr + lrow)) * 192 + tc * 64 + col4 * 4;
        float4 yv = *(const float4*)(Y + gaddr);
        float bb = up_b[oc];
        float4 o = make_float4(s.x + bb + gamma * yv.x, s.y + bb + gamma * yv.y,
                               s.z + bb + gamma * yv.z, s.w + bb + gamma * yv.w);
        *(float4*)(out + gaddr) = o;
    }
}

// ----------------- launch -----------------
extern "C" void kernel_launch(void* const* d_in, const int* in_sizes, int n_in,
                              void* d_out, int out_size) {
    (void)in_sizes; (void)n_in; (void)out_size;
    const float* input_x = (const float*)d_in[0];
    const float* input_y = (const float*)d_in[1];
    const float* down0_w = (const float*)d_in[2];
    const float* down0_b = (const float*)d_in[3];
    const float* down1_w = (const float*)d_in[4];
    const float* down1_b = (const float*)d_in[5];
    const float* theta_w = (const float*)d_in[6];
    const float* phi_w   = (const float*)d_in[7];
    const float* g_w     = (const float*)d_in[8];
    const float* o_w     = (const float*)d_in[9];
    const float* up_w    = (const float*)d_in[10];
    const float* up_b    = (const float*)d_in[11];
    const float* gamma   = (const float*)d_in[12];
    float* out = (float*)d_out;

    cudaFuncSetAttribute(conv_tp, cudaFuncAttributeMaxDynamicSharedMemorySize, 67584);
    cudaFuncSetAttribute(conv_g, cudaFuncAttributeMaxDynamicSharedMemorySize, 51200);
    cudaFuncSetAttribute(attn_tc, cudaFuncAttributeMaxDynamicSharedMemorySize, 64512);
    cudaFuncSetAttribute(out_k, cudaFuncAttributeMaxDynamicSharedMemorySize, 67584);

    fuse_all<<<128, 256>>>(theta_w, phi_w, g_w, o_w,
                           down0_w, down0_b, down1_w, down1_b, up_w);
    conv_tp<<<dim3(3, 24, 4), 256, 67584>>>(input_x);
    conv_g<<<dim3(3, 24, 4), 256, 51200>>>(input_y);
    attn_tc<<<dim3(144, 4), 128, 64512>>>();
    out_k<<<dim3(3, 24, 16), 256, 67584>>>(input_y, up_b, gamma, out);
}